// round 10
// baseline (speedup 1.0000x reference)
#include <cuda_runtime.h>
#include <cuda_fp16.h>
#include <math.h>
#include <stdint.h>

#define BB   8
#define NN   8192
#define SS   2048
#define C1c  128
#define C2c  256
#define CIN  384
#define TT   256
#define CO   256
#define COUNT_BN (BB*NN)

// ---------------- scratch (device globals) ----------------
__device__ float  d_p2t[BB*SS*C2c];                 // points2 transposed (B,S,C2)
__device__ int    d_idx3[BB*NN*3];
__device__ float  d_w3[BB*NN*3];
__device__ __half d_itph[(size_t)BB*C2c*NN];        // interpolated channels, fp16
__device__ __half d_y1h[(size_t)BB*CO*NN];          // layer1 output, fp16
__device__ __half d_y2h[(size_t)BB*CO*NN];          // layer2 raw output, fp16
__device__ float  d_bias1[BB*CO];
__device__ float  d_bias2[BB*CO];
__device__ float  d_sum1[CO], d_sq1[CO], d_sum2[CO], d_sq2[CO];
__device__ float  d_a1[CO], d_b1[CO], d_a2[CO], d_b2[CO];
// fp16 A images in m16n8k16 fragment order
__device__ __half d_w1img[CO*CIN];
__device__ __half d_w2img[CO*CO];

#define TPBLK (64*8*BB)   // transpose blocks: (SS/32)*(C2c/32)*BB = 64*8*8 = 4096

__device__ __forceinline__ float gelu_exact(float x) {
    return 0.5f * x * (1.0f + erff(x * 0.7071067811865476f));
}
__device__ __forceinline__ uint32_t smem_u32(const void* p) {
    uint32_t a;
    asm("{ .reg .u64 tmp; cvta.to.shared.u64 tmp, %1; cvt.u32.u64 %0, tmp; }" : "=r"(a) : "l"(p));
    return a;
}
__device__ __forceinline__ void cp16(uint32_t dst, const void* src) {
    asm volatile("cp.async.cg.shared.global [%0], [%1], 16;" :: "r"(dst), "l"(src));
}
__device__ __forceinline__ void cp_commit() { asm volatile("cp.async.commit_group;" ::: "memory"); }
__device__ __forceinline__ void cp_wait0()  { asm volatile("cp.async.wait_group 0;" ::: "memory"); }

#define MMA_F16(d, a, b0, b1)                                                     \
    asm volatile("mma.sync.aligned.m16n8k16.row.col.f32.f16.f16.f32 "             \
                 "{%0,%1,%2,%3}, {%4,%5,%6,%7}, {%8,%9}, {%0,%1,%2,%3};"          \
                 : "+f"(d[0]), "+f"(d[1]), "+f"(d[2]), "+f"(d[3])                 \
                 : "r"(a.x), "r"(a.y), "r"(a.z), "r"(a.w), "r"(b0), "r"(b1))

// ---------------- weight permute body (fp16 m16n8k16 fragment order) ----------------
__device__ __forceinline__ void permA16_body(const float* __restrict__ w,
                                             __half* __restrict__ img, int K, int idx)
{
    int o = idx / K, k = idx % K;
    int bm = o >> 4, r = o & 15;
    int g = r & 7, hi = r >> 3;
    int kt = k >> 5, kl = k & 31;
    int bk = kl >> 4, kk = kl & 15;
    int tq  = (kk & 7) >> 1;
    int khi = kk >> 3;
    int klo = kk & 1;
    int lane = g*4 + tq;
    int reg  = hi + 2*khi;
    size_t uidx = ((size_t)(kt*16 + bm)*2 + bk)*128 + lane*4 + reg;
    img[uidx*2 + klo] = __float2half_rn(w[idx]);
}

// ---------------- merged prep: t-cond biases + A images + p2 transpose + stat zero ----------------
__global__ void __launch_bounds__(384) prep_all(
    const float* __restrict__ t_embed, const float* __restrict__ points2,
    const float* __restrict__ w_t1, const float* __restrict__ b_t1,
    const float* __restrict__ w_c1, const float* __restrict__ b_c1,
    const float* __restrict__ w_t2, const float* __restrict__ b_t2,
    const float* __restrict__ w_c2, const float* __restrict__ b_c2)
{
    int blk = blockIdx.x, t = threadIdx.x;
    if (blk < BB) {
        int b = blk;
        __shared__ float g[TT];
        __shared__ float te1[CIN];
        __shared__ float te2[CO];
        if (t < TT) g[t] = gelu_exact(t_embed[b*TT + t]);
        __syncthreads();
        {
            float s = b_t1[t];
            const float* w = w_t1 + (size_t)t*TT;
            #pragma unroll 8
            for (int k = 0; k < TT; k++) s = fmaf(g[k], w[k], s);
            te1[t] = s;
        }
        if (t < CO) {
            float s = b_t2[t];
            const float* w = w_t2 + (size_t)t*TT;
            #pragma unroll 8
            for (int k = 0; k < TT; k++) s = fmaf(g[k], w[k], s);
            te2[t] = s;
        }
        __syncthreads();
        if (t < CO) {
            float s1 = b_c1[t];
            const float* w1 = w_c1 + (size_t)t*CIN;
            #pragma unroll 8
            for (int k = 0; k < CIN; k++) s1 = fmaf(te1[k], w1[k], s1);
            d_bias1[b*CO + t] = s1;
            float s2 = b_c2[t];
            const float* w2 = w_c2 + (size_t)t*CO;
            #pragma unroll 8
            for (int k = 0; k < CO; k++) s2 = fmaf(te2[k], w2[k], s2);
            d_bias2[b*CO + t] = s2;
        }
        if (b == 0 && t < CO) {
            d_sum1[t] = 0.f; d_sq1[t] = 0.f; d_sum2[t] = 0.f; d_sq2[t] = 0.f;
        }
    } else if (blk < BB + 256) {
        int idx = (blk - BB)*384 + t;
        if (idx < CO*CIN) permA16_body(w_c1, d_w1img, CIN, idx);
    } else if (blk < BB + 256 + 171) {
        int idx = (blk - BB - 256)*384 + t;
        if (idx < CO*CO) permA16_body(w_c2, d_w2img, CO, idx);
    } else {
        // points2 transpose (B,C2,S) -> (B,S,C2), 32x32 tile per block, 256 active threads
        __shared__ float tile[32][33];
        int tb = blk - (BB + 256 + 171);
        int b  = tb >> 9;                 // / 512
        int r  = tb & 511;
        int s0 = (r & 63) * 32;           // 64 s-tiles
        int c0 = (r >> 6) * 32;           // 8 c-tiles
        if (t < 256) {
            int tx = t & 31, ty = t >> 5; // 32 x 8
            const float* src = points2 + (size_t)b*C2c*SS;
            float*       dst = d_p2t   + (size_t)b*SS*C2c;
            #pragma unroll
            for (int j = 0; j < 32; j += 8)
                tile[ty+j][tx] = src[(size_t)(c0+ty+j)*SS + s0 + tx];
            __syncthreads();
            #pragma unroll
            for (int j = 0; j < 32; j += 8)
                dst[(size_t)(s0+ty+j)*C2c + c0 + tx] = tile[tx][ty+j];
        } else {
            __syncthreads();
        }
    }
}

// ---------------- 3-NN: 2 query points per thread ----------------
__global__ void __launch_bounds__(256) top3_kernel(const float* __restrict__ xyz1,
                                                   const float* __restrict__ xyz2)
{
    __shared__ float4 sq[SS];
    int b = blockIdx.y;
    const float* x2 = xyz2 + (size_t)b*SS*3;
    for (int i = threadIdx.x; i < SS; i += 256) {
        float a = x2[i*3+0], bb = x2[i*3+1], c = x2[i*3+2];
        float4 q;
        q.x = -2.0f*a; q.y = -2.0f*bb; q.z = -2.0f*c;
        q.w = a*a + bb*bb + c*c;
        sq[i] = q;
    }
    __syncthreads();
    int nA = blockIdx.x * 512 + threadIdx.x;
    int nB = nA + 256;
    const float* pA = xyz1 + ((size_t)b*NN + nA)*3;
    const float* pB = xyz1 + ((size_t)b*NN + nB)*3;
    float ax = pA[0], ay = pA[1], az = pA[2];
    float bx = pB[0], by = pB[1], bz = pB[2];
    float nna = ax*ax + ay*ay + az*az;
    float nnb = bx*bx + by*by + bz*bz;
    float aE0 = 3.4e38f, aE1 = 3.4e38f, aE2 = 3.4e38f;
    float bE0 = 3.4e38f, bE1 = 3.4e38f, bE2 = 3.4e38f;
    int   aI0 = 0, aI1 = 0, aI2 = 0, bI0 = 0, bI1 = 0, bI2 = 0;
    #pragma unroll 4
    for (int s = 0; s < SS; s++) {
        float4 q = sq[s];
        float eA = fmaf(ax, q.x, fmaf(ay, q.y, fmaf(az, q.z, q.w)));
        float eB = fmaf(bx, q.x, fmaf(by, q.y, fmaf(bz, q.z, q.w)));
        if (eA < aE2) {
            aE2 = eA; aI2 = s;
            if (aE2 < aE1) {
                float te = aE1; aE1 = aE2; aE2 = te;
                int ti = aI1; aI1 = aI2; aI2 = ti;
                if (aE1 < aE0) {
                    te = aE0; aE0 = aE1; aE1 = te;
                    ti = aI0; aI0 = aI1; aI1 = ti;
                }
            }
        }
        if (eB < bE2) {
            bE2 = eB; bI2 = s;
            if (bE2 < bE1) {
                float te = bE1; bE1 = bE2; bE2 = te;
                int ti = bI1; bI1 = bI2; bI2 = ti;
                if (bE1 < bE0) {
                    te = bE0; bE0 = bE1; bE1 = te;
                    ti = bI0; bI0 = bI1; bI1 = ti;
                }
            }
        }
    }
    {
        float d0 = nna + aE0, d1 = nna + aE1, d2 = nna + aE2;
        float r0 = 1.f/(d0 + 1e-8f), r1 = 1.f/(d1 + 1e-8f), r2 = 1.f/(d2 + 1e-8f);
        float inv = 1.f/(r0 + r1 + r2);
        size_t base = ((size_t)b*NN + nA)*3;
        d_idx3[base+0] = aI0; d_idx3[base+1] = aI1; d_idx3[base+2] = aI2;
        d_w3[base+0] = r0*inv; d_w3[base+1] = r1*inv; d_w3[base+2] = r2*inv;
    }
    {
        float d0 = nnb + bE0, d1 = nnb + bE1, d2 = nnb + bE2;
        float r0 = 1.f/(d0 + 1e-8f), r1 = 1.f/(d1 + 1e-8f), r2 = 1.f/(d2 + 1e-8f);
        float inv = 1.f/(r0 + r1 + r2);
        size_t base = ((size_t)b*NN + nB)*3;
        d_idx3[base+0] = bI0; d_idx3[base+1] = bI1; d_idx3[base+2] = bI2;
        d_w3[base+0] = r0*inv; d_w3[base+1] = r1*inv; d_w3[base+2] = r2*inv;
    }
}

// ---------------- 3-NN interpolation into d_itph (B,256,N) fp16 ----------------
__global__ void __launch_bounds__(256) interp_kernel()
{
    __shared__ __half sc[C2c][34];
    __shared__ int    sidx[32*3];
    __shared__ float  swt[32*3];
    int b  = blockIdx.y;
    int n0 = blockIdx.x * 32;
    int t  = threadIdx.x;
    if (t < 96) {
        size_t base = ((size_t)b*NN + n0)*3;
        sidx[t] = d_idx3[base + t];
        swt[t]  = d_w3[base + t];
    }
    __syncthreads();
    const float* p2t = d_p2t + (size_t)b*SS*C2c;
    #pragma unroll 4
    for (int nl = 0; nl < 32; nl++) {
        int   j0 = sidx[nl*3+0], j1 = sidx[nl*3+1], j2 = sidx[nl*3+2];
        float w0 = swt[nl*3+0],  w1 = swt[nl*3+1],  w2 = swt[nl*3+2];
        float v = fmaf(w2, p2t[(size_t)j2*C2c + t],
                  fmaf(w1, p2t[(size_t)j1*C2c + t],
                       w0 * p2t[(size_t)j0*C2c + t]));
        sc[t][nl] = __float2half_rn(v);
    }
    __syncthreads();
    __half* xout = d_itph + (size_t)b*C2c*NN + n0;
    int nl2 = (t & 15) * 2;
    int c0  = t >> 4;
    #pragma unroll
    for (int c = c0; c < C2c; c += 16) {
        __half2 hv;
        hv.x = sc[c][nl2];
        hv.y = sc[c][nl2 + 1];
        *(__half2*)(xout + (size_t)c*NN + nl2) = hv;
    }
}

// ---------------- fp16 tensor-core GEMM (R6 verbatim) ----------------
// Block tile M=256 x N=64, K chunked by 32. 8 warps: wm(4) x wn(2); warp 64x32.
// Layer1 (L2MODE=false): B = points1 (fp32) for k<128, d_itph (fp16) for k>=128.
// Layer2 (L2MODE=true):  B = y1h (fp16), BN1+GELU fused on load.
template<int KTOT, bool L2MODE>
__global__ void __launch_bounds__(256) gemm_f16(
    const __half* __restrict__ AimgH,
    const float* __restrict__ Xp1,      // layer1: points1 (fp32)
    const __half* __restrict__ Xh,      // layer1: itph / layer2: y1h
    __half* __restrict__ Yh,
    const float* __restrict__ bias,
    const float* __restrict__ ain, const float* __restrict__ bin,
    float* __restrict__ sumOut, float* __restrict__ sqOut)
{
    constexpr int NC = KTOT / 32;
    __shared__ __align__(16) uint4    As[2][1024];   // 16KB per buffer
    __shared__ __align__(16) uint32_t Bs[2][1024];   // 4KB per buffer
    __shared__ float redS[CO], redQ[CO];

    const uint32_t* Aimg = (const uint32_t*)AimgH;
    int t = threadIdx.x, l = t & 31, w = t >> 5;
    int wm = w >> 1, wn = w & 1;
    int g = l >> 2, tq = l & 3;
    int b = blockIdx.y, nT = blockIdx.x * 64;

    redS[t] = 0.f; redQ[t] = 0.f;

    int kp = t >> 4, n4 = t & 15;    // staging: k-pair row (0..15), n-quad (0..15)

    float acc[4][4][4];
    #pragma unroll
    for (int i = 0; i < 4; i++)
        #pragma unroll
        for (int j = 0; j < 4; j++)
            #pragma unroll
            for (int r = 0; r < 4; r++) acc[i][j][r] = 0.f;

    float pv[8];
    auto stageB = [&](int c) {
        int k0 = c*32 + 2*kp;
        bool useH = L2MODE || (k0 >= C1c);
        if (useH) {
            int kk = L2MODE ? k0 : (k0 - C1c);
            const __half* bh = Xh + (size_t)b*C2c*NN + (size_t)kk*NN + nT + 4*n4;
            uint2 u0 = *(const uint2*)bh;
            uint2 u1 = *(const uint2*)(bh + NN);
            __half2 h;
            h = *(__half2*)&u0.x; pv[0] = __low2float(h); pv[1] = __high2float(h);
            h = *(__half2*)&u0.y; pv[2] = __low2float(h); pv[3] = __high2float(h);
            h = *(__half2*)&u1.x; pv[4] = __low2float(h); pv[5] = __high2float(h);
            h = *(__half2*)&u1.y; pv[6] = __low2float(h); pv[7] = __high2float(h);
        } else {
            const float* base = Xp1 + (size_t)b*C1c*NN + (size_t)k0*NN + nT + 4*n4;
            float4 v0 = *(const float4*)base;
            float4 v1 = *(const float4*)(base + NN);
            pv[0] = v0.x; pv[1] = v0.y; pv[2] = v0.z; pv[3] = v0.w;
            pv[4] = v1.x; pv[5] = v1.y; pv[6] = v1.z; pv[7] = v1.w;
        }
    };
    auto storeB = [&](int c, int buf) {
        float f[8];
        #pragma unroll
        for (int j = 0; j < 8; j++) f[j] = pv[j];
        if (L2MODE) {
            int kg0 = c*32 + 2*kp;
            float a0 = ain[kg0],   b0 = bin[kg0];
            float a1 = ain[kg0+1], b1 = bin[kg0+1];
            #pragma unroll
            for (int j = 0; j < 4; j++) f[j]   = gelu_exact(fmaf(a0, f[j],   b0));
            #pragma unroll
            for (int j = 0; j < 4; j++) f[j+4] = gelu_exact(fmaf(a1, f[j+4], b1));
        }
        uint4 u;
        __half2 h;
        h = __floats2half2_rn(f[0], f[4]); u.x = *(uint32_t*)&h;
        h = __floats2half2_rn(f[1], f[5]); u.y = *(uint32_t*)&h;
        h = __floats2half2_rn(f[2], f[6]); u.z = *(uint32_t*)&h;
        h = __floats2half2_rn(f[3], f[7]); u.w = *(uint32_t*)&h;
        ((uint4*)Bs[buf])[kp*16 + (n4 ^ ((kp & 3) << 1))] = u;
    };
    auto stageA = [&](int c, int buf) {
        const uint32_t* src = Aimg + (size_t)c*4096 + t*4;
        uint32_t base = smem_u32(&As[buf][0]);
        #pragma unroll
        for (int j = 0; j < 4; j++)
            cp16(base + (uint32_t)(t + j*256)*16u, src + j*1024);
    };
    auto compute = [&](int buf) {
        uint4 af[4][2];
        #pragma unroll
        for (int mf = 0; mf < 4; mf++)
            #pragma unroll
            for (int bk = 0; bk < 2; bk++)
                af[mf][bk] = As[buf][((wm*4 + mf)*2 + bk)*32 + l];
        uint32_t bf[4][2][2];
        #pragma unroll
        for (int bnl = 0; bnl < 4; bnl++) {
            int n = wn*32 + bnl*8 + g;
            int nsw = n ^ (tq << 3);
            #pragma unroll
            for (int bk = 0; bk < 2; bk++) {
                bf[bnl][bk][0] = Bs[buf][(bk*8 + tq)*64 + nsw];
                bf[bnl][bk][1] = Bs[buf][(bk*8 + tq + 4)*64 + nsw];
            }
        }
        #pragma unroll
        for (int mf = 0; mf < 4; mf++)
            #pragma unroll
            for (int bnl = 0; bnl < 4; bnl++)
                #pragma unroll
                for (int bk = 0; bk < 2; bk++)
                    MMA_F16(acc[mf][bnl], af[mf][bk], bf[bnl][bk][0], bf[bnl][bk][1]);
    };

    // pipeline
    stageB(0);
    stageA(0, 0); cp_commit();
    storeB(0, 0);
    for (int c = 0; c < NC; c++) {
        int buf = c & 1;
        cp_wait0();
        __syncthreads();
        if (c + 1 < NC) { stageB(c + 1); stageA(c + 1, buf ^ 1); cp_commit(); }
        compute(buf);
        if (c + 1 < NC) storeB(c + 1, buf ^ 1);
    }

    // ---- epilogue: bias, fp16 store, stats ----
    #pragma unroll
    for (int mf = 0; mf < 4; mf++) {
        int o_lo = wm*64 + mf*16 + g;
        int o_hi = o_lo + 8;
        float bl = bias[b*CO + o_lo];
        float bh = bias[b*CO + o_hi];
        float sl = 0.f, ql = 0.f, sh = 0.f, qh = 0.f;
        #pragma unroll
        for (int bnl = 0; bnl < 4; bnl++) {
            int col = nT + wn*32 + bnl*8 + 2*tq;
            float v0 = acc[mf][bnl][0] + bl;
            float v1 = acc[mf][bnl][1] + bl;
            float v2 = acc[mf][bnl][2] + bh;
            float v3 = acc[mf][bnl][3] + bh;
            __half2 hlo = __floats2half2_rn(v0, v1);
            __half2 hhi = __floats2half2_rn(v2, v3);
            *(__half2*)(Yh + (size_t)b*CO*NN + (size_t)o_lo*NN + col) = hlo;
            *(__half2*)(Yh + (size_t)b*CO*NN + (size_t)o_hi*NN + col) = hhi;
            sl += v0 + v1; ql += v0*v0 + v1*v1;
            sh += v2 + v3; qh += v2*v2 + v3*v3;
        }
        #pragma unroll
        for (int off = 1; off <= 2; off <<= 1) {
            sl += __shfl_xor_sync(0xffffffffu, sl, off);
            ql += __shfl_xor_sync(0xffffffffu, ql, off);
            sh += __shfl_xor_sync(0xffffffffu, sh, off);
            qh += __shfl_xor_sync(0xffffffffu, qh, off);
        }
        if (tq == 0) {
            atomicAdd(&redS[o_lo], sl);
            atomicAdd(&redQ[o_lo], ql);
            atomicAdd(&redS[o_hi], sh);
            atomicAdd(&redQ[o_hi], qh);
        }
    }
    __syncthreads();
    atomicAdd(&sumOut[t], redS[t]);
    atomicAdd(&sqOut[t],  redQ[t]);
}

// ---------------- BN scale/shift finalize ----------------
__global__ void bn_finalize(const float* __restrict__ sum, const float* __restrict__ sq,
                            const float* __restrict__ gamma, const float* __restrict__ beta,
                            float* __restrict__ aOut, float* __restrict__ bOut)
{
    int c = threadIdx.x;
    float m = sum[c] * (1.0f/COUNT_BN);
    float v = sq[c]  * (1.0f/COUNT_BN) - m*m;
    float inv = rsqrtf(v + 1e-5f);
    float a = gamma[c] * inv;
    aOut[c] = a;
    bOut[c] = beta[c] - a*m;
}

// ---------------- final: out = gelu(a2[c]*y2h + b2[c]) -> fp32 ----------------
__global__ void __launch_bounds__(256) final_kernel(const __half* __restrict__ y2h,
                                                    float* __restrict__ out)
{
    size_t i8 = (size_t)blockIdx.x * 256 + threadIdx.x;
    size_t total8 = (size_t)BB*CO*NN/8;
    if (i8 >= total8) return;
    uint4 u = ((const uint4*)y2h)[i8];
    size_t i = i8 * 8;
    int c = (int)((i >> 13) & 255);
    float a = d_a2[c], bo = d_b2[c];
    const __half2* hp = (const __half2*)&u;
    float4 o0, o1;
    float2 f;
    f = __half22float2(hp[0]); o0.x = gelu_exact(fmaf(a, f.x, bo)); o0.y = gelu_exact(fmaf(a, f.y, bo));
    f = __half22float2(hp[1]); o0.z = gelu_exact(fmaf(a, f.x, bo)); o0.w = gelu_exact(fmaf(a, f.y, bo));
    f = __half22float2(hp[2]); o1.x = gelu_exact(fmaf(a, f.x, bo)); o1.y = gelu_exact(fmaf(a, f.y, bo));
    f = __half22float2(hp[3]); o1.z = gelu_exact(fmaf(a, f.x, bo)); o1.w = gelu_exact(fmaf(a, f.y, bo));
    ((float4*)out)[i8*2 + 0] = o0;
    ((float4*)out)[i8*2 + 1] = o1;
}

// ---------------- launch ----------------
extern "C" void kernel_launch(void* const* d_in, const int* in_sizes, int n_in,
                              void* d_out, int out_size)
{
    const float* xyz1    = (const float*)d_in[0];
    const float* xyz2    = (const float*)d_in[1];
    const float* points1 = (const float*)d_in[2];
    const float* points2 = (const float*)d_in[3];
    const float* t_embed = (const float*)d_in[4];
    const float* w_t1 = (const float*)d_in[5];
    const float* b_t1 = (const float*)d_in[6];
    const float* w_c1 = (const float*)d_in[7];
    const float* b_c1 = (const float*)d_in[8];
    const float* g1   = (const float*)d_in[9];
    const float* be1  = (const float*)d_in[10];
    const float* w_t2 = (const float*)d_in[11];
    const float* b_t2 = (const float*)d_in[12];
    const float* w_c2 = (const float*)d_in[13];
    const float* b_c2 = (const float*)d_in[14];
    const float* g2   = (const float*)d_in[15];
    const float* be2  = (const float*)d_in[16];
    float* out = (float*)d_out;

    float *p_bias1, *p_bias2;
    float *p_sum1, *p_sq1, *p_sum2, *p_sq2, *p_a1, *p_b1, *p_a2, *p_b2;
    __half *p_itph, *p_y1h, *p_y2h, *p_w1i, *p_w2i;
    cudaGetSymbolAddress((void**)&p_itph,  d_itph);
    cudaGetSymbolAddress((void**)&p_y1h,   d_y1h);
    cudaGetSymbolAddress((void**)&p_y2h,   d_y2h);
    cudaGetSymbolAddress((void**)&p_bias1, d_bias1);
    cudaGetSymbolAddress((void**)&p_bias2, d_bias2);
    cudaGetSymbolAddress((void**)&p_sum1,  d_sum1);
    cudaGetSymbolAddress((void**)&p_sq1,   d_sq1);
    cudaGetSymbolAddress((void**)&p_sum2,  d_sum2);
    cudaGetSymbolAddress((void**)&p_sq2,   d_sq2);
    cudaGetSymbolAddress((void**)&p_a1,    d_a1);
    cudaGetSymbolAddress((void**)&p_b1,    d_b1);
    cudaGetSymbolAddress((void**)&p_a2,    d_a2);
    cudaGetSymbolAddress((void**)&p_b2,    d_b2);
    cudaGetSymbolAddress((void**)&p_w1i,   d_w1img);
    cudaGetSymbolAddress((void**)&p_w2i,   d_w2img);

    // prep blocks: 8 bias + 256 perm1 + 171 perm2 + 4096 transpose
    prep_all<<<BB + 256 + 171 + TPBLK, 384>>>(t_embed, points2,
                                              w_t1, b_t1, w_c1, b_c1,
                                              w_t2, b_t2, w_c2, b_c2);
    top3_kernel<<<dim3(NN/512, BB), 256>>>(xyz1, xyz2);
    interp_kernel<<<dim3(NN/32, BB), 256>>>();

    // Layer 1: y1h = fp16(w_c1 @ [points1; itph] + bias1)
    gemm_f16<CIN, false><<<dim3(NN/64, BB), 256>>>(
        p_w1i, points1, p_itph, p_y1h,
        p_bias1, nullptr, nullptr, p_sum1, p_sq1);
    bn_finalize<<<1, 256>>>(p_sum1, p_sq1, g1, be1, p_a1, p_b1);

    // Layer 2: y2h = fp16(w_c2 @ gelu(bn1(y1h)) + bias2)
    gemm_f16<CO, true><<<dim3(NN/64, BB), 256>>>(
        p_w2i, (const float*)nullptr, p_y1h, p_y2h,
        p_bias2, p_a1, p_b1, p_sum2, p_sq2);
    bn_finalize<<<1, 256>>>(p_sum2, p_sq2, g2, be2, p_a2, p_b2);

    final_kernel<<<(unsigned)(((size_t)BB*CO*NN/8 + 255)/256), 256>>>(p_y2h, out);
}

// round 11
// speedup vs baseline: 1.0453x; 1.0453x over previous
#include <cuda_runtime.h>
#include <cuda_fp16.h>
#include <math.h>
#include <stdint.h>

#define BB   8
#define NN   8192
#define SS   2048
#define C1c  128
#define C2c  256
#define CIN  384
#define TT   256
#define CO   256
#define COUNT_BN (BB*NN)

// ---------------- scratch (device globals) ----------------
__device__ float  d_p2t[BB*SS*C2c];                 // points2 transposed (B,S,C2)
__device__ int    d_idx3[BB*NN*3];
__device__ float  d_w3[BB*NN*3];
__device__ __half d_itph[(size_t)BB*C2c*NN];        // interpolated channels, fp16
__device__ __half d_y1h[(size_t)BB*CO*NN];          // layer1 output, fp16
__device__ __half d_y2h[(size_t)BB*CO*NN];          // layer2 raw output, fp16
__device__ float  d_bias1[BB*CO];
__device__ float  d_bias2[BB*CO];
__device__ float  d_sum1[CO], d_sq1[CO], d_sum2[CO], d_sq2[CO];
__device__ float  d_a1[CO], d_b1[CO], d_a2[CO], d_b2[CO];
// fp16 A images in m16n8k16 fragment order
__device__ __half d_w1img[CO*CIN];
__device__ __half d_w2img[CO*CO];

__device__ __forceinline__ float gelu_exact(float x) {
    return 0.5f * x * (1.0f + erff(x * 0.7071067811865476f));
}
__device__ __forceinline__ uint32_t smem_u32(const void* p) {
    uint32_t a;
    asm("{ .reg .u64 tmp; cvta.to.shared.u64 tmp, %1; cvt.u32.u64 %0, tmp; }" : "=r"(a) : "l"(p));
    return a;
}
__device__ __forceinline__ void cp16(uint32_t dst, const void* src) {
    asm volatile("cp.async.cg.shared.global [%0], [%1], 16;" :: "r"(dst), "l"(src));
}
__device__ __forceinline__ void cp_commit() { asm volatile("cp.async.commit_group;" ::: "memory"); }
__device__ __forceinline__ void cp_wait0()  { asm volatile("cp.async.wait_group 0;" ::: "memory"); }

#define MMA_F16(d, a, b0, b1)                                                     \
    asm volatile("mma.sync.aligned.m16n8k16.row.col.f32.f16.f16.f32 "             \
                 "{%0,%1,%2,%3}, {%4,%5,%6,%7}, {%8,%9}, {%0,%1,%2,%3};"          \
                 : "+f"(d[0]), "+f"(d[1]), "+f"(d[2]), "+f"(d[3])                 \
                 : "r"(a.x), "r"(a.y), "r"(a.z), "r"(a.w), "r"(b0), "r"(b1))

// ---------------- weight permute body (fp16 m16n8k16 fragment order) ----------------
__device__ __forceinline__ void permA16_body(const float* __restrict__ w,
                                             __half* __restrict__ img, int K, int idx)
{
    int o = idx / K, k = idx % K;
    int bm = o >> 4, r = o & 15;
    int g = r & 7, hi = r >> 3;
    int kt = k >> 5, kl = k & 31;
    int bk = kl >> 4, kk = kl & 15;
    int tq  = (kk & 7) >> 1;
    int khi = kk >> 3;
    int klo = kk & 1;
    int lane = g*4 + tq;
    int reg  = hi + 2*khi;
    size_t uidx = ((size_t)(kt*16 + bm)*2 + bk)*128 + lane*4 + reg;
    img[uidx*2 + klo] = __float2half_rn(w[idx]);
}

// ---------------- merged weight prep: t-cond biases + both A images + stat zero ----------------
__global__ void __launch_bounds__(384) prep_all(
    const float* __restrict__ t_embed,
    const float* __restrict__ w_t1, const float* __restrict__ b_t1,
    const float* __restrict__ w_c1, const float* __restrict__ b_c1,
    const float* __restrict__ w_t2, const float* __restrict__ b_t2,
    const float* __restrict__ w_c2, const float* __restrict__ b_c2)
{
    int blk = blockIdx.x, t = threadIdx.x;
    if (blk < BB) {
        int b = blk;
        __shared__ float g[TT];
        __shared__ float te1[CIN];
        __shared__ float te2[CO];
        if (t < TT) g[t] = gelu_exact(t_embed[b*TT + t]);
        __syncthreads();
        {
            float s = b_t1[t];
            const float* w = w_t1 + (size_t)t*TT;
            #pragma unroll 8
            for (int k = 0; k < TT; k++) s = fmaf(g[k], w[k], s);
            te1[t] = s;
        }
        if (t < CO) {
            float s = b_t2[t];
            const float* w = w_t2 + (size_t)t*TT;
            #pragma unroll 8
            for (int k = 0; k < TT; k++) s = fmaf(g[k], w[k], s);
            te2[t] = s;
        }
        __syncthreads();
        if (t < CO) {
            float s1 = b_c1[t];
            const float* w1 = w_c1 + (size_t)t*CIN;
            #pragma unroll 8
            for (int k = 0; k < CIN; k++) s1 = fmaf(te1[k], w1[k], s1);
            d_bias1[b*CO + t] = s1;
            float s2 = b_c2[t];
            const float* w2 = w_c2 + (size_t)t*CO;
            #pragma unroll 8
            for (int k = 0; k < CO; k++) s2 = fmaf(te2[k], w2[k], s2);
            d_bias2[b*CO + t] = s2;
        }
        if (b == 0 && t < CO) {
            d_sum1[t] = 0.f; d_sq1[t] = 0.f; d_sum2[t] = 0.f; d_sq2[t] = 0.f;
        }
    } else if (blk < BB + 256) {
        int idx = (blk - BB)*384 + t;
        if (idx < CO*CIN) permA16_body(w_c1, d_w1img, CIN, idx);
    } else {
        int idx = (blk - BB - 256)*384 + t;
        if (idx < CO*CO) permA16_body(w_c2, d_w2img, CO, idx);
    }
}

// ---------------- transpose points2 (B,C2,S) -> (B,S,C2) ----------------
__global__ void transpose_p2(const float* __restrict__ p2)
{
    __shared__ float tile[32][33];
    int b  = blockIdx.z;
    int s0 = blockIdx.x * 32;
    int c0 = blockIdx.y * 32;
    int tx = threadIdx.x, ty = threadIdx.y;
    const float* src = p2    + (size_t)b*C2c*SS;
    float*       dst = d_p2t + (size_t)b*SS*C2c;
    #pragma unroll
    for (int j = 0; j < 32; j += 8)
        tile[ty+j][tx] = src[(size_t)(c0+ty+j)*SS + s0 + tx];
    __syncthreads();
    #pragma unroll
    for (int j = 0; j < 32; j += 8)
        dst[(size_t)(s0+ty+j)*C2c + c0 + tx] = tile[tx][ty+j];
}

// ---------------- 3-NN (R6: one point per thread, e-form, float4 smem) ----------------
__global__ void __launch_bounds__(256) top3_kernel(const float* __restrict__ xyz1,
                                                   const float* __restrict__ xyz2)
{
    __shared__ float4 sq[SS];   // (-2x, -2y, -2z, |q|^2) : 32KB
    int b = blockIdx.y;
    const float* x2 = xyz2 + (size_t)b*SS*3;
    for (int i = threadIdx.x; i < SS; i += 256) {
        float a = x2[i*3+0], bb = x2[i*3+1], c = x2[i*3+2];
        float4 q;
        q.x = -2.0f*a; q.y = -2.0f*bb; q.z = -2.0f*c;
        q.w = a*a + bb*bb + c*c;
        sq[i] = q;
    }
    __syncthreads();
    int n = blockIdx.x * 256 + threadIdx.x;
    const float* p = xyz1 + ((size_t)b*NN + n)*3;
    float px = p[0], py = p[1], pz = p[2];
    float n1 = px*px + py*py + pz*pz;
    float e0 = 3.4e38f, e1 = 3.4e38f, e2 = 3.4e38f;
    int   i0 = 0, i1 = 0, i2 = 0;
    #pragma unroll 4
    for (int s = 0; s < SS; s++) {
        float4 q = sq[s];
        float e = fmaf(px, q.x, fmaf(py, q.y, fmaf(pz, q.z, q.w)));
        if (e < e2) {
            e2 = e; i2 = s;
            if (e2 < e1) {
                float te = e1; e1 = e2; e2 = te;
                int   ti = i1; i1 = i2; i2 = ti;
                if (e1 < e0) {
                    te = e0; e0 = e1; e1 = te;
                    ti = i0; i0 = i1; i1 = ti;
                }
            }
        }
    }
    float d0 = n1 + e0, d1 = n1 + e1, d2 = n1 + e2;
    float r0 = 1.f/(d0 + 1e-8f), r1 = 1.f/(d1 + 1e-8f), r2 = 1.f/(d2 + 1e-8f);
    float inv = 1.f/(r0 + r1 + r2);
    size_t base = ((size_t)b*NN + n)*3;
    d_idx3[base+0] = i0; d_idx3[base+1] = i1; d_idx3[base+2] = i2;
    d_w3[base+0] = r0*inv; d_w3[base+1] = r1*inv; d_w3[base+2] = r2*inv;
}

// ---------------- 3-NN interpolation into d_itph (B,256,N) fp16 ----------------
__global__ void __launch_bounds__(256) interp_kernel()
{
    __shared__ __half sc[C2c][34];
    __shared__ int    sidx[32*3];
    __shared__ float  swt[32*3];
    int b  = blockIdx.y;
    int n0 = blockIdx.x * 32;
    int t  = threadIdx.x;
    if (t < 96) {
        size_t base = ((size_t)b*NN + n0)*3;
        sidx[t] = d_idx3[base + t];
        swt[t]  = d_w3[base + t];
    }
    __syncthreads();
    const float* p2t = d_p2t + (size_t)b*SS*C2c;
    #pragma unroll 4
    for (int nl = 0; nl < 32; nl++) {
        int   j0 = sidx[nl*3+0], j1 = sidx[nl*3+1], j2 = sidx[nl*3+2];
        float w0 = swt[nl*3+0],  w1 = swt[nl*3+1],  w2 = swt[nl*3+2];
        float v = fmaf(w2, p2t[(size_t)j2*C2c + t],
                  fmaf(w1, p2t[(size_t)j1*C2c + t],
                       w0 * p2t[(size_t)j0*C2c + t]));
        sc[t][nl] = __float2half_rn(v);
    }
    __syncthreads();
    __half* xout = d_itph + (size_t)b*C2c*NN + n0;
    int nl2 = (t & 15) * 2;
    int c0  = t >> 4;
    #pragma unroll
    for (int c = c0; c < C2c; c += 16) {
        __half2 hv;
        hv.x = sc[c][nl2];
        hv.y = sc[c][nl2 + 1];
        *(__half2*)(xout + (size_t)c*NN + nl2) = hv;
    }
}

// ---------------- fp16 tensor-core GEMM: R6 pipeline, M split in halves ----------------
// CTA tile M=128 (half h = blockIdx.y) x N=64, K chunked by 32.
// 8 warps: wm(4) x wn(2); warp tile 32x32. acc = 32 regs/thread.
template<int KTOT, bool L2MODE>
__global__ void __launch_bounds__(256) gemm_f16(
    const __half* __restrict__ AimgH,
    const float* __restrict__ Xp1,      // layer1: points1 (fp32)
    const __half* __restrict__ Xh,      // layer1: itph / layer2: y1h
    __half* __restrict__ Yh,
    const float* __restrict__ bias,
    const float* __restrict__ ain, const float* __restrict__ bin,
    float* __restrict__ sumOut, float* __restrict__ sqOut)
{
    constexpr int NC = KTOT / 32;
    __shared__ __align__(16) uint4    As[2][512];    // 8KB per buffer (M=128)
    __shared__ __align__(16) uint32_t Bs[2][1024];   // 4KB per buffer
    __shared__ float redS[128], redQ[128];

    const uint32_t* Aimg = (const uint32_t*)AimgH;
    int t = threadIdx.x, l = t & 31, w = t >> 5;
    int wm = w >> 1, wn = w & 1;
    int g = l >> 2, tq = l & 3;
    int b = blockIdx.z, h = blockIdx.y, nT = blockIdx.x * 64;

    if (t < 128) { redS[t] = 0.f; redQ[t] = 0.f; }

    int kp = t >> 4, n4 = t & 15;    // staging: k-pair row (0..15), n-quad (0..15)

    float acc[2][4][4];
    #pragma unroll
    for (int i = 0; i < 2; i++)
        #pragma unroll
        for (int j = 0; j < 4; j++)
            #pragma unroll
            for (int r = 0; r < 4; r++) acc[i][j][r] = 0.f;

    float pv[8];
    auto stageB = [&](int c) {
        int k0 = c*32 + 2*kp;
        bool useH = L2MODE || (k0 >= C1c);
        if (useH) {
            int kk = L2MODE ? k0 : (k0 - C1c);
            const __half* bh = Xh + (size_t)b*C2c*NN + (size_t)kk*NN + nT + 4*n4;
            uint2 u0 = *(const uint2*)bh;
            uint2 u1 = *(const uint2*)(bh + NN);
            __half2 hh;
            hh = *(__half2*)&u0.x; pv[0] = __low2float(hh); pv[1] = __high2float(hh);
            hh = *(__half2*)&u0.y; pv[2] = __low2float(hh); pv[3] = __high2float(hh);
            hh = *(__half2*)&u1.x; pv[4] = __low2float(hh); pv[5] = __high2float(hh);
            hh = *(__half2*)&u1.y; pv[6] = __low2float(hh); pv[7] = __high2float(hh);
        } else {
            const float* base = Xp1 + (size_t)b*C1c*NN + (size_t)k0*NN + nT + 4*n4;
            float4 v0 = *(const float4*)base;
            float4 v1 = *(const float4*)(base + NN);
            pv[0] = v0.x; pv[1] = v0.y; pv[2] = v0.z; pv[3] = v0.w;
            pv[4] = v1.x; pv[5] = v1.y; pv[6] = v1.z; pv[7] = v1.w;
        }
    };
    auto storeB = [&](int c, int buf) {
        float f[8];
        #pragma unroll
        for (int j = 0; j < 8; j++) f[j] = pv[j];
        if (L2MODE) {
            int kg0 = c*32 + 2*kp;
            float a0 = ain[kg0],   b0 = bin[kg0];
            float a1 = ain[kg0+1], b1 = bin[kg0+1];
            #pragma unroll
            for (int j = 0; j < 4; j++) f[j]   = gelu_exact(fmaf(a0, f[j],   b0));
            #pragma unroll
            for (int j = 0; j < 4; j++) f[j+4] = gelu_exact(fmaf(a1, f[j+4], b1));
        }
        uint4 u;
        __half2 hh;
        hh = __floats2half2_rn(f[0], f[4]); u.x = *(uint32_t*)&hh;
        hh = __floats2half2_rn(f[1], f[5]); u.y = *(uint32_t*)&hh;
        hh = __floats2half2_rn(f[2], f[6]); u.z = *(uint32_t*)&hh;
        hh = __floats2half2_rn(f[3], f[7]); u.w = *(uint32_t*)&hh;
        ((uint4*)Bs[buf])[kp*16 + (n4 ^ ((kp & 3) << 1))] = u;
    };
    auto stageA = [&](int c, int buf) {
        // half h: 2048 u32 (8KB) per chunk, linear
        const uint32_t* src = Aimg + (size_t)c*4096 + (size_t)h*2048 + t*4;
        uint32_t base = smem_u32(&As[buf][0]);
        cp16(base + (uint32_t)t*16u,          src);
        cp16(base + (uint32_t)(t + 256)*16u,  src + 1024);
    };
    auto compute = [&](int buf) {
        uint4 af[2][2];
        #pragma unroll
        for (int mf = 0; mf < 2; mf++)
            #pragma unroll
            for (int bk = 0; bk < 2; bk++)
                af[mf][bk] = As[buf][((wm*2 + mf)*2 + bk)*32 + l];
        uint32_t bf[4][2][2];
        #pragma unroll
        for (int bnl = 0; bnl < 4; bnl++) {
            int n = wn*32 + bnl*8 + g;
            int nsw = n ^ (tq << 3);
            #pragma unroll
            for (int bk = 0; bk < 2; bk++) {
                bf[bnl][bk][0] = Bs[buf][(bk*8 + tq)*64 + nsw];
                bf[bnl][bk][1] = Bs[buf][(bk*8 + tq + 4)*64 + nsw];
            }
        }
        #pragma unroll
        for (int mf = 0; mf < 2; mf++)
            #pragma unroll
            for (int bnl = 0; bnl < 4; bnl++)
                #pragma unroll
                for (int bk = 0; bk < 2; bk++)
                    MMA_F16(acc[mf][bnl], af[mf][bk], bf[bnl][bk][0], bf[bnl][bk][1]);
    };

    // ---- R6 pipeline ----
    stageB(0);
    stageA(0, 0); cp_commit();
    storeB(0, 0);
    for (int c = 0; c < NC; c++) {
        int buf = c & 1;
        cp_wait0();
        __syncthreads();
        if (c + 1 < NC) { stageB(c + 1); stageA(c + 1, buf ^ 1); cp_commit(); }
        compute(buf);
        if (c + 1 < NC) storeB(c + 1, buf ^ 1);
    }

    // ---- epilogue: bias, fp16 store, stats ----
    #pragma unroll
    for (int mf = 0; mf < 2; mf++) {
        int ol_lo = wm*32 + mf*16 + g;      // local row 0..127
        int ol_hi = ol_lo + 8;
        int o_lo = h*128 + ol_lo;
        int o_hi = h*128 + ol_hi;
        float bl = bias[b*CO + o_lo];
        float bh = bias[b*CO + o_hi];
        float sl = 0.f, ql = 0.f, sh = 0.f, qh = 0.f;
        #pragma unroll
        for (int bnl = 0; bnl < 4; bnl++) {
            int col = nT + wn*32 + bnl*8 + 2*tq;
            float v0 = acc[mf][bnl][0] + bl;
            float v1 = acc[mf][bnl][1] + bl;
            float v2 = acc[mf][bnl][2] + bh;
            float v3 = acc[mf][bnl][3] + bh;
            __half2 hlo = __floats2half2_rn(v0, v1);
            __half2 hhi = __floats2half2_rn(v2, v3);
            *(__half2*)(Yh + (size_t)b*CO*NN + (size_t)o_lo*NN + col) = hlo;
            *(__half2*)(Yh + (size_t)b*CO*NN + (size_t)o_hi*NN + col) = hhi;
            sl += v0 + v1; ql += v0*v0 + v1*v1;
            sh += v2 + v3; qh += v2*v2 + v3*v3;
        }
        #pragma unroll
        for (int off = 1; off <= 2; off <<= 1) {
            sl += __shfl_xor_sync(0xffffffffu, sl, off);
            ql += __shfl_xor_sync(0xffffffffu, ql, off);
            sh += __shfl_xor_sync(0xffffffffu, sh, off);
            qh += __shfl_xor_sync(0xffffffffu, qh, off);
        }
        if (tq == 0) {
            atomicAdd(&redS[ol_lo], sl);
            atomicAdd(&redQ[ol_lo], ql);
            atomicAdd(&redS[ol_hi], sh);
            atomicAdd(&redQ[ol_hi], qh);
        }
    }
    __syncthreads();
    if (t < 128) {
        atomicAdd(&sumOut[h*128 + t], redS[t]);
        atomicAdd(&sqOut[h*128 + t],  redQ[t]);
    }
}

// ---------------- BN scale/shift finalize ----------------
__global__ void bn_finalize(const float* __restrict__ sum, const float* __restrict__ sq,
                            const float* __restrict__ gamma, const float* __restrict__ beta,
                            float* __restrict__ aOut, float* __restrict__ bOut)
{
    int c = threadIdx.x;
    float m = sum[c] * (1.0f/COUNT_BN);
    float v = sq[c]  * (1.0f/COUNT_BN) - m*m;
    float inv = rsqrtf(v + 1e-5f);
    float a = gamma[c] * inv;
    aOut[c] = a;
    bOut[c] = beta[c] - a*m;
}

// ---------------- final: out = gelu(a2[c]*y2h + b2[c]) -> fp32 ----------------
__global__ void __launch_bounds__(256) final_kernel(const __half* __restrict__ y2h,
                                                    float* __restrict__ out)
{
    size_t i8 = (size_t)blockIdx.x * 256 + threadIdx.x;
    size_t total8 = (size_t)BB*CO*NN/8;
    if (i8 >= total8) return;
    uint4 u = ((const uint4*)y2h)[i8];
    size_t i = i8 * 8;
    int c = (int)((i >> 13) & 255);
    float a = d_a2[c], bo = d_b2[c];
    const __half2* hp = (const __half2*)&u;
    float4 o0, o1;
    float2 f;
    f = __half22float2(hp[0]); o0.x = gelu_exact(fmaf(a, f.x, bo)); o0.y = gelu_exact(fmaf(a, f.y, bo));
    f = __half22float2(hp[1]); o0.z = gelu_exact(fmaf(a, f.x, bo)); o0.w = gelu_exact(fmaf(a, f.y, bo));
    f = __half22float2(hp[2]); o1.x = gelu_exact(fmaf(a, f.x, bo)); o1.y = gelu_exact(fmaf(a, f.y, bo));
    f = __half22float2(hp[3]); o1.z = gelu_exact(fmaf(a, f.x, bo)); o1.w = gelu_exact(fmaf(a, f.y, bo));
    ((float4*)out)[i8*2 + 0] = o0;
    ((float4*)out)[i8*2 + 1] = o1;
}

// ---------------- launch ----------------
extern "C" void kernel_launch(void* const* d_in, const int* in_sizes, int n_in,
                              void* d_out, int out_size)
{
    const float* xyz1    = (const float*)d_in[0];
    const float* xyz2    = (const float*)d_in[1];
    const float* points1 = (const float*)d_in[2];
    const float* points2 = (const float*)d_in[3];
    const float* t_embed = (const float*)d_in[4];
    const float* w_t1 = (const float*)d_in[5];
    const float* b_t1 = (const float*)d_in[6];
    const float* w_c1 = (const float*)d_in[7];
    const float* b_c1 = (const float*)d_in[8];
    const float* g1   = (const float*)d_in[9];
    const float* be1  = (const float*)d_in[10];
    const float* w_t2 = (const float*)d_in[11];
    const float* b_t2 = (const float*)d_in[12];
    const float* w_c2 = (const float*)d_in[13];
    const float* b_c2 = (const float*)d_in[14];
    const float* g2   = (const float*)d_in[15];
    const float* be2  = (const float*)d_in[16];
    float* out = (float*)d_out;

    float *p_bias1, *p_bias2;
    float *p_sum1, *p_sq1, *p_sum2, *p_sq2, *p_a1, *p_b1, *p_a2, *p_b2;
    __half *p_itph, *p_y1h, *p_y2h, *p_w1i, *p_w2i;
    cudaGetSymbolAddress((void**)&p_itph,  d_itph);
    cudaGetSymbolAddress((void**)&p_y1h,   d_y1h);
    cudaGetSymbolAddress((void**)&p_y2h,   d_y2h);
    cudaGetSymbolAddress((void**)&p_bias1, d_bias1);
    cudaGetSymbolAddress((void**)&p_bias2, d_bias2);
    cudaGetSymbolAddress((void**)&p_sum1,  d_sum1);
    cudaGetSymbolAddress((void**)&p_sq1,   d_sq1);
    cudaGetSymbolAddress((void**)&p_sum2,  d_sum2);
    cudaGetSymbolAddress((void**)&p_sq2,   d_sq2);
    cudaGetSymbolAddress((void**)&p_a1,    d_a1);
    cudaGetSymbolAddress((void**)&p_b1,    d_b1);
    cudaGetSymbolAddress((void**)&p_a2,    d_a2);
    cudaGetSymbolAddress((void**)&p_b2,    d_b2);
    cudaGetSymbolAddress((void**)&p_w1i,   d_w1img);
    cudaGetSymbolAddress((void**)&p_w2i,   d_w2img);

    prep_all<<<BB + 256 + 171, 384>>>(t_embed, w_t1, b_t1, w_c1, b_c1,
                                      w_t2, b_t2, w_c2, b_c2);
    transpose_p2<<<dim3(SS/32, C2c/32, BB), dim3(32, 8)>>>(points2);
    top3_kernel<<<dim3(NN/256, BB), 256>>>(xyz1, xyz2);
    interp_kernel<<<dim3(NN/32, BB), 256>>>();

    // Layer 1: y1h = fp16(w_c1 @ [points1; itph] + bias1)
    gemm_f16<CIN, false><<<dim3(NN/64, 2, BB), 256>>>(
        p_w1i, points1, p_itph, p_y1h,
        p_bias1, nullptr, nullptr, p_sum1, p_sq1);
    bn_finalize<<<1, 256>>>(p_sum1, p_sq1, g1, be1, p_a1, p_b1);

    // Layer 2: y2h = fp16(w_c2 @ gelu(bn1(y1h)) + bias2)
    gemm_f16<CO, true><<<dim3(NN/64, 2, BB), 256>>>(
        p_w2i, (const float*)nullptr, p_y1h, p_y2h,
        p_bias2, p_a1, p_b1, p_sum2, p_sq2);
    bn_finalize<<<1, 256>>>(p_sum2, p_sq2, g2, be2, p_a2, p_b2);

    final_kernel<<<(unsigned)(((size_t)BB*CO*NN/8 + 255)/256), 256>>>(p_y2h, out);
}

// round 12
// speedup vs baseline: 1.2178x; 1.1650x over previous
#include <cuda_runtime.h>
#include <cuda_fp16.h>
#include <math.h>
#include <stdint.h>

#define BB   8
#define NN   8192
#define SS   2048
#define C1c  128
#define C2c  256
#define CIN  384
#define TT   256
#define CO   256
#define COUNT_BN (BB*NN)

// ---------------- scratch (device globals) ----------------
__device__ float  d_p2t[BB*SS*C2c];                 // points2 transposed (B,S,C2)
__device__ int    d_idx3[BB*NN*3];
__device__ float  d_w3[BB*NN*3];
__device__ __half d_itph[(size_t)BB*C2c*NN];        // interpolated channels, fp16
__device__ __half d_y1h[(size_t)BB*CO*NN];          // layer1 output, fp16
__device__ __half d_y2h[(size_t)BB*CO*NN];          // layer2 raw output, fp16
__device__ float  d_bias1[BB*CO];
__device__ float  d_bias2[BB*CO];
__device__ float  d_sum1[CO], d_sq1[CO], d_sum2[CO], d_sq2[CO];
// fp16 A images in m16n8k16 fragment order
__device__ __half d_w1img[CO*CIN];
__device__ __half d_w2img[CO*CO];

// mega-kernel block ranges
#define MB_TOP3   256                    // (NN/256)*BB = 32*8
#define MB_TRANS  4096                   // 64*8*BB
#define MB_PERM1  384                    // CO*CIN/256
#define MB_PERM2  256                    // CO*CO/256
#define MB_BIAS   BB
#define MB_TOTAL  (MB_TOP3 + MB_TRANS + MB_PERM1 + MB_PERM2 + MB_BIAS)   // 5000

__device__ __forceinline__ float gelu_exact(float x) {
    return 0.5f * x * (1.0f + erff(x * 0.7071067811865476f));
}
__device__ __forceinline__ uint32_t smem_u32(const void* p) {
    uint32_t a;
    asm("{ .reg .u64 tmp; cvta.to.shared.u64 tmp, %1; cvt.u32.u64 %0, tmp; }" : "=r"(a) : "l"(p));
    return a;
}
__device__ __forceinline__ void cp16(uint32_t dst, const void* src) {
    asm volatile("cp.async.cg.shared.global [%0], [%1], 16;" :: "r"(dst), "l"(src));
}
__device__ __forceinline__ void cp_commit() { asm volatile("cp.async.commit_group;" ::: "memory"); }
__device__ __forceinline__ void cp_wait0()  { asm volatile("cp.async.wait_group 0;" ::: "memory"); }

#define MMA_F16(d, a, b0, b1)                                                     \
    asm volatile("mma.sync.aligned.m16n8k16.row.col.f32.f16.f16.f32 "             \
                 "{%0,%1,%2,%3}, {%4,%5,%6,%7}, {%8,%9}, {%0,%1,%2,%3};"          \
                 : "+f"(d[0]), "+f"(d[1]), "+f"(d[2]), "+f"(d[3])                 \
                 : "r"(a.x), "r"(a.y), "r"(a.z), "r"(a.w), "r"(b0), "r"(b1))

// ---------------- weight permute body (fp16 m16n8k16 fragment order) ----------------
__device__ __forceinline__ void permA16_body(const float* __restrict__ w,
                                             __half* __restrict__ img, int K, int idx)
{
    int o = idx / K, k = idx % K;
    int bm = o >> 4, r = o & 15;
    int g = r & 7, hi = r >> 3;
    int kt = k >> 5, kl = k & 31;
    int bk = kl >> 4, kk = kl & 15;
    int tq  = (kk & 7) >> 1;
    int khi = kk >> 3;
    int klo = kk & 1;
    int lane = g*4 + tq;
    int reg  = hi + 2*khi;
    size_t uidx = ((size_t)(kt*16 + bm)*2 + bk)*128 + lane*4 + reg;
    img[uidx*2 + klo] = __float2half_rn(w[idx]);
}

// ---------------- mega: top3 + transpose + weight perms + t-cond biases + stat zero ----------------
__global__ void __launch_bounds__(256) mega_prep(
    const float* __restrict__ xyz1, const float* __restrict__ xyz2,
    const float* __restrict__ points2, const float* __restrict__ t_embed,
    const float* __restrict__ w_t1, const float* __restrict__ b_t1,
    const float* __restrict__ w_c1, const float* __restrict__ b_c1,
    const float* __restrict__ w_t2, const float* __restrict__ b_t2,
    const float* __restrict__ w_c2, const float* __restrict__ b_c2)
{
    __shared__ __align__(16) char smem_raw[32768];
    int blk = blockIdx.x, t = threadIdx.x;

    if (blk < MB_TOP3) {
        // ---- 3-NN top3 (R6 verbatim: 1 point/thread, e-form, float4 smem) ----
        float4* sq = (float4*)smem_raw;           // SS entries = 32KB
        int b = blk >> 5;                          // 32 n-blocks per batch
        int nblk = blk & 31;
        const float* x2 = xyz2 + (size_t)b*SS*3;
        for (int i = t; i < SS; i += 256) {
            float a = x2[i*3+0], bb = x2[i*3+1], c = x2[i*3+2];
            float4 q;
            q.x = -2.0f*a; q.y = -2.0f*bb; q.z = -2.0f*c;
            q.w = a*a + bb*bb + c*c;
            sq[i] = q;
        }
        __syncthreads();
        int n = nblk * 256 + t;
        const float* p = xyz1 + ((size_t)b*NN + n)*3;
        float px = p[0], py = p[1], pz = p[2];
        float n1 = px*px + py*py + pz*pz;
        float e0 = 3.4e38f, e1 = 3.4e38f, e2 = 3.4e38f;
        int   i0 = 0, i1 = 0, i2 = 0;
        #pragma unroll 4
        for (int s = 0; s < SS; s++) {
            float4 q = sq[s];
            float e = fmaf(px, q.x, fmaf(py, q.y, fmaf(pz, q.z, q.w)));
            if (e < e2) {
                e2 = e; i2 = s;
                if (e2 < e1) {
                    float te = e1; e1 = e2; e2 = te;
                    int   ti = i1; i1 = i2; i2 = ti;
                    if (e1 < e0) {
                        te = e0; e0 = e1; e1 = te;
                        ti = i0; i0 = i1; i1 = ti;
                    }
                }
            }
        }
        float d0 = n1 + e0, d1 = n1 + e1, d2 = n1 + e2;
        float r0 = 1.f/(d0 + 1e-8f), r1 = 1.f/(d1 + 1e-8f), r2 = 1.f/(d2 + 1e-8f);
        float inv = 1.f/(r0 + r1 + r2);
        size_t base = ((size_t)b*NN + n)*3;
        d_idx3[base+0] = i0; d_idx3[base+1] = i1; d_idx3[base+2] = i2;
        d_w3[base+0] = r0*inv; d_w3[base+1] = r1*inv; d_w3[base+2] = r2*inv;
    } else if (blk < MB_TOP3 + MB_TRANS) {
        // ---- points2 transpose (B,C2,S) -> (B,S,C2) ----
        typedef float Tile[33];
        Tile* tile = (Tile*)smem_raw;
        int tb = blk - MB_TOP3;
        int b  = tb >> 9;
        int r  = tb & 511;
        int s0 = (r & 63) * 32;
        int c0 = (r >> 6) * 32;
        int tx = t & 31, ty = t >> 5;   // 32 x 8
        const float* src = points2 + (size_t)b*C2c*SS;
        float*       dst = d_p2t   + (size_t)b*SS*C2c;
        #pragma unroll
        for (int j = 0; j < 32; j += 8)
            tile[ty+j][tx] = src[(size_t)(c0+ty+j)*SS + s0 + tx];
        __syncthreads();
        #pragma unroll
        for (int j = 0; j < 32; j += 8)
            dst[(size_t)(s0+ty+j)*C2c + c0 + tx] = tile[tx][ty+j];
    } else if (blk < MB_TOP3 + MB_TRANS + MB_PERM1) {
        int idx = (blk - MB_TOP3 - MB_TRANS)*256 + t;
        permA16_body(w_c1, d_w1img, CIN, idx);
    } else if (blk < MB_TOP3 + MB_TRANS + MB_PERM1 + MB_PERM2) {
        int idx = (blk - MB_TOP3 - MB_TRANS - MB_PERM1)*256 + t;
        permA16_body(w_c2, d_w2img, CO, idx);
    } else {
        // ---- t-cond bias folding (256 threads) + stat zero ----
        float* g   = (float*)smem_raw;          // 256
        float* te1 = g + TT;                    // 384
        float* te2 = te1 + CIN;                 // 256
        int b = blk - (MB_TOP3 + MB_TRANS + MB_PERM1 + MB_PERM2);
        g[t] = gelu_exact(t_embed[b*TT + t]);
        __syncthreads();
        for (int c = t; c < CIN; c += 256) {
            float s = b_t1[c];
            const float* w = w_t1 + (size_t)c*TT;
            #pragma unroll 8
            for (int k = 0; k < TT; k++) s = fmaf(g[k], w[k], s);
            te1[c] = s;
        }
        {
            float s = b_t2[t];
            const float* w = w_t2 + (size_t)t*TT;
            #pragma unroll 8
            for (int k = 0; k < TT; k++) s = fmaf(g[k], w[k], s);
            te2[t] = s;
        }
        __syncthreads();
        {
            float s1 = b_c1[t];
            const float* w1 = w_c1 + (size_t)t*CIN;
            #pragma unroll 8
            for (int k = 0; k < CIN; k++) s1 = fmaf(te1[k], w1[k], s1);
            d_bias1[b*CO + t] = s1;
            float s2 = b_c2[t];
            const float* w2 = w_c2 + (size_t)t*CO;
            #pragma unroll 8
            for (int k = 0; k < CO; k++) s2 = fmaf(te2[k], w2[k], s2);
            d_bias2[b*CO + t] = s2;
        }
        if (b == 0) {
            d_sum1[t] = 0.f; d_sq1[t] = 0.f; d_sum2[t] = 0.f; d_sq2[t] = 0.f;
        }
    }
}

// ---------------- 3-NN interpolation into d_itph (B,256,N) fp16 ----------------
__global__ void __launch_bounds__(256) interp_kernel()
{
    __shared__ __half sc[C2c][34];
    __shared__ int    sidx[32*3];
    __shared__ float  swt[32*3];
    int b  = blockIdx.y;
    int n0 = blockIdx.x * 32;
    int t  = threadIdx.x;
    if (t < 96) {
        size_t base = ((size_t)b*NN + n0)*3;
        sidx[t] = d_idx3[base + t];
        swt[t]  = d_w3[base + t];
    }
    __syncthreads();
    const float* p2t = d_p2t + (size_t)b*SS*C2c;
    #pragma unroll 4
    for (int nl = 0; nl < 32; nl++) {
        int   j0 = sidx[nl*3+0], j1 = sidx[nl*3+1], j2 = sidx[nl*3+2];
        float w0 = swt[nl*3+0],  w1 = swt[nl*3+1],  w2 = swt[nl*3+2];
        float v = fmaf(w2, p2t[(size_t)j2*C2c + t],
                  fmaf(w1, p2t[(size_t)j1*C2c + t],
                       w0 * p2t[(size_t)j0*C2c + t]));
        sc[t][nl] = __float2half_rn(v);
    }
    __syncthreads();
    __half* xout = d_itph + (size_t)b*C2c*NN + n0;
    int nl2 = (t & 15) * 2;
    int c0  = t >> 4;
    #pragma unroll
    for (int c = c0; c < C2c; c += 16) {
        __half2 hv;
        hv.x = sc[c][nl2];
        hv.y = sc[c][nl2 + 1];
        *(__half2*)(xout + (size_t)c*NN + nl2) = hv;
    }
}

// ---------------- fp16 tensor-core GEMM (R6 verbatim; L2MODE computes BN1 in-kernel) ----------------
// Block tile M=256 x N=64, K chunked by 32. 8 warps: wm(4) x wn(2); warp 64x32.
template<int KTOT, bool L2MODE>
__global__ void __launch_bounds__(256) gemm_f16(
    const __half* __restrict__ AimgH,
    const float* __restrict__ Xp1,      // layer1: points1 (fp32)
    const __half* __restrict__ Xh,      // layer1: itph / layer2: y1h
    __half* __restrict__ Yh,
    const float* __restrict__ bias,
    const float* __restrict__ sumIn, const float* __restrict__ sqIn,
    const float* __restrict__ gamma, const float* __restrict__ beta,
    float* __restrict__ sumOut, float* __restrict__ sqOut)
{
    constexpr int NC = KTOT / 32;
    __shared__ __align__(16) uint4    As[2][1024];   // 16KB per buffer
    __shared__ __align__(16) uint32_t Bs[2][1024];   // 4KB per buffer
    __shared__ float redS[CO], redQ[CO];
    __shared__ float sA[CO], sB[CO];                 // BN1 scale/shift (L2MODE)

    const uint32_t* Aimg = (const uint32_t*)AimgH;
    int t = threadIdx.x, l = t & 31, w = t >> 5;
    int wm = w >> 1, wn = w & 1;
    int g = l >> 2, tq = l & 3;
    int b = blockIdx.y, nT = blockIdx.x * 64;

    redS[t] = 0.f; redQ[t] = 0.f;
    if (L2MODE) {
        float m = sumIn[t] * (1.0f/COUNT_BN);
        float v = sqIn[t]  * (1.0f/COUNT_BN) - m*m;
        float inv = rsqrtf(v + 1e-5f);
        float a = gamma[t] * inv;
        sA[t] = a;
        sB[t] = beta[t] - a*m;
    }
    __syncthreads();

    int kp = t >> 4, n4 = t & 15;    // staging: k-pair row (0..15), n-quad (0..15)

    float acc[4][4][4];
    #pragma unroll
    for (int i = 0; i < 4; i++)
        #pragma unroll
        for (int j = 0; j < 4; j++)
            #pragma unroll
            for (int r = 0; r < 4; r++) acc[i][j][r] = 0.f;

    float pv[8];
    auto stageB = [&](int c) {
        int k0 = c*32 + 2*kp;
        bool useH = L2MODE || (k0 >= C1c);
        if (useH) {
            int kk = L2MODE ? k0 : (k0 - C1c);
            const __half* bh = Xh + (size_t)b*C2c*NN + (size_t)kk*NN + nT + 4*n4;
            uint2 u0 = *(const uint2*)bh;
            uint2 u1 = *(const uint2*)(bh + NN);
            __half2 h;
            h = *(__half2*)&u0.x; pv[0] = __low2float(h); pv[1] = __high2float(h);
            h = *(__half2*)&u0.y; pv[2] = __low2float(h); pv[3] = __high2float(h);
            h = *(__half2*)&u1.x; pv[4] = __low2float(h); pv[5] = __high2float(h);
            h = *(__half2*)&u1.y; pv[6] = __low2float(h); pv[7] = __high2float(h);
        } else {
            const float* base = Xp1 + (size_t)b*C1c*NN + (size_t)k0*NN + nT + 4*n4;
            float4 v0 = *(const float4*)base;
            float4 v1 = *(const float4*)(base + NN);
            pv[0] = v0.x; pv[1] = v0.y; pv[2] = v0.z; pv[3] = v0.w;
            pv[4] = v1.x; pv[5] = v1.y; pv[6] = v1.z; pv[7] = v1.w;
        }
    };
    auto storeB = [&](int c, int buf) {
        float f[8];
        #pragma unroll
        for (int j = 0; j < 8; j++) f[j] = pv[j];
        if (L2MODE) {
            int kg0 = c*32 + 2*kp;
            float a0 = sA[kg0],   b0 = sB[kg0];
            float a1 = sA[kg0+1], b1 = sB[kg0+1];
            #pragma unroll
            for (int j = 0; j < 4; j++) f[j]   = gelu_exact(fmaf(a0, f[j],   b0));
            #pragma unroll
            for (int j = 0; j < 4; j++) f[j+4] = gelu_exact(fmaf(a1, f[j+4], b1));
        }
        uint4 u;
        __half2 h;
        h = __floats2half2_rn(f[0], f[4]); u.x = *(uint32_t*)&h;
        h = __floats2half2_rn(f[1], f[5]); u.y = *(uint32_t*)&h;
        h = __floats2half2_rn(f[2], f[6]); u.z = *(uint32_t*)&h;
        h = __floats2half2_rn(f[3], f[7]); u.w = *(uint32_t*)&h;
        ((uint4*)Bs[buf])[kp*16 + (n4 ^ ((kp & 3) << 1))] = u;
    };
    auto stageA = [&](int c, int buf) {
        const uint32_t* src = Aimg + (size_t)c*4096 + t*4;
        uint32_t base = smem_u32(&As[buf][0]);
        #pragma unroll
        for (int j = 0; j < 4; j++)
            cp16(base + (uint32_t)(t + j*256)*16u, src + j*1024);
    };
    auto compute = [&](int buf) {
        uint4 af[4][2];
        #pragma unroll
        for (int mf = 0; mf < 4; mf++)
            #pragma unroll
            for (int bk = 0; bk < 2; bk++)
                af[mf][bk] = As[buf][((wm*4 + mf)*2 + bk)*32 + l];
        uint32_t bf[4][2][2];
        #pragma unroll
        for (int bnl = 0; bnl < 4; bnl++) {
            int n = wn*32 + bnl*8 + g;
            int nsw = n ^ (tq << 3);
            #pragma unroll
            for (int bk = 0; bk < 2; bk++) {
                bf[bnl][bk][0] = Bs[buf][(bk*8 + tq)*64 + nsw];
                bf[bnl][bk][1] = Bs[buf][(bk*8 + tq + 4)*64 + nsw];
            }
        }
        #pragma unroll
        for (int mf = 0; mf < 4; mf++)
            #pragma unroll
            for (int bnl = 0; bnl < 4; bnl++)
                #pragma unroll
                for (int bk = 0; bk < 2; bk++)
                    MMA_F16(acc[mf][bnl], af[mf][bk], bf[bnl][bk][0], bf[bnl][bk][1]);
    };

    // ---- R6 pipeline ----
    stageB(0);
    stageA(0, 0); cp_commit();
    storeB(0, 0);
    for (int c = 0; c < NC; c++) {
        int buf = c & 1;
        cp_wait0();
        __syncthreads();
        if (c + 1 < NC) { stageB(c + 1); stageA(c + 1, buf ^ 1); cp_commit(); }
        compute(buf);
        if (c + 1 < NC) storeB(c + 1, buf ^ 1);
    }

    // ---- epilogue: bias, fp16 store, stats ----
    #pragma unroll
    for (int mf = 0; mf < 4; mf++) {
        int o_lo = wm*64 + mf*16 + g;
        int o_hi = o_lo + 8;
        float bl = bias[b*CO + o_lo];
        float bh = bias[b*CO + o_hi];
        float sl = 0.f, ql = 0.f, sh = 0.f, qh = 0.f;
        #pragma unroll
        for (int bnl = 0; bnl < 4; bnl++) {
            int col = nT + wn*32 + bnl*8 + 2*tq;
            float v0 = acc[mf][bnl][0] + bl;
            float v1 = acc[mf][bnl][1] + bl;
            float v2 = acc[mf][bnl][2] + bh;
            float v3 = acc[mf][bnl][3] + bh;
            __half2 hlo = __floats2half2_rn(v0, v1);
            __half2 hhi = __floats2half2_rn(v2, v3);
            *(__half2*)(Yh + (size_t)b*CO*NN + (size_t)o_lo*NN + col) = hlo;
            *(__half2*)(Yh + (size_t)b*CO*NN + (size_t)o_hi*NN + col) = hhi;
            sl += v0 + v1; ql += v0*v0 + v1*v1;
            sh += v2 + v3; qh += v2*v2 + v3*v3;
        }
        #pragma unroll
        for (int off = 1; off <= 2; off <<= 1) {
            sl += __shfl_xor_sync(0xffffffffu, sl, off);
            ql += __shfl_xor_sync(0xffffffffu, ql, off);
            sh += __shfl_xor_sync(0xffffffffu, sh, off);
            qh += __shfl_xor_sync(0xffffffffu, qh, off);
        }
        if (tq == 0) {
            atomicAdd(&redS[o_lo], sl);
            atomicAdd(&redQ[o_lo], ql);
            atomicAdd(&redS[o_hi], sh);
            atomicAdd(&redQ[o_hi], qh);
        }
    }
    __syncthreads();
    atomicAdd(&sumOut[t], redS[t]);
    atomicAdd(&sqOut[t],  redQ[t]);
}

// ---------------- final: BN2 finalize + gelu in one pass, fp16 -> fp32 ----------------
__global__ void __launch_bounds__(256) final_kernel(
    const __half* __restrict__ y2h,
    const float* __restrict__ sum2, const float* __restrict__ sq2,
    const float* __restrict__ gamma, const float* __restrict__ beta,
    float* __restrict__ out)
{
    size_t i8 = (size_t)blockIdx.x * 256 + threadIdx.x;
    size_t total8 = (size_t)BB*CO*NN/8;
    if (i8 >= total8) return;
    uint4 u = ((const uint4*)y2h)[i8];
    size_t i = i8 * 8;
    int c = (int)((i >> 13) & 255);
    float m = sum2[c] * (1.0f/COUNT_BN);
    float v = sq2[c]  * (1.0f/COUNT_BN) - m*m;
    float inv = rsqrtf(v + 1e-5f);
    float a = gamma[c] * inv;
    float bo = beta[c] - a*m;
    const __half2* hp = (const __half2*)&u;
    float4 o0, o1;
    float2 f;
    f = __half22float2(hp[0]); o0.x = gelu_exact(fmaf(a, f.x, bo)); o0.y = gelu_exact(fmaf(a, f.y, bo));
    f = __half22float2(hp[1]); o0.z = gelu_exact(fmaf(a, f.x, bo)); o0.w = gelu_exact(fmaf(a, f.y, bo));
    f = __half22float2(hp[2]); o1.x = gelu_exact(fmaf(a, f.x, bo)); o1.y = gelu_exact(fmaf(a, f.y, bo));
    f = __half22float2(hp[3]); o1.z = gelu_exact(fmaf(a, f.x, bo)); o1.w = gelu_exact(fmaf(a, f.y, bo));
    ((float4*)out)[i8*2 + 0] = o0;
    ((float4*)out)[i8*2 + 1] = o1;
}

// ---------------- launch ----------------
extern "C" void kernel_launch(void* const* d_in, const int* in_sizes, int n_in,
                              void* d_out, int out_size)
{
    const float* xyz1    = (const float*)d_in[0];
    const float* xyz2    = (const float*)d_in[1];
    const float* points1 = (const float*)d_in[2];
    const float* points2 = (const float*)d_in[3];
    const float* t_embed = (const float*)d_in[4];
    const float* w_t1 = (const float*)d_in[5];
    const float* b_t1 = (const float*)d_in[6];
    const float* w_c1 = (const float*)d_in[7];
    const float* b_c1 = (const float*)d_in[8];
    const float* g1   = (const float*)d_in[9];
    const float* be1  = (const float*)d_in[10];
    const float* w_t2 = (const float*)d_in[11];
    const float* b_t2 = (const float*)d_in[12];
    const float* w_c2 = (const float*)d_in[13];
    const float* b_c2 = (const float*)d_in[14];
    const float* g2   = (const float*)d_in[15];
    const float* be2  = (const float*)d_in[16];
    float* out = (float*)d_out;

    float *p_bias1, *p_bias2;
    float *p_sum1, *p_sq1, *p_sum2, *p_sq2;
    __half *p_itph, *p_y1h, *p_y2h, *p_w1i, *p_w2i;
    cudaGetSymbolAddress((void**)&p_itph,  d_itph);
    cudaGetSymbolAddress((void**)&p_y1h,   d_y1h);
    cudaGetSymbolAddress((void**)&p_y2h,   d_y2h);
    cudaGetSymbolAddress((void**)&p_bias1, d_bias1);
    cudaGetSymbolAddress((void**)&p_bias2, d_bias2);
    cudaGetSymbolAddress((void**)&p_sum1,  d_sum1);
    cudaGetSymbolAddress((void**)&p_sq1,   d_sq1);
    cudaGetSymbolAddress((void**)&p_sum2,  d_sum2);
    cudaGetSymbolAddress((void**)&p_sq2,   d_sq2);
    cudaGetSymbolAddress((void**)&p_w1i,   d_w1img);
    cudaGetSymbolAddress((void**)&p_w2i,   d_w2img);

    // 1. mega-prep: top3 + transpose + weight perms + biases + stat zero
    mega_prep<<<MB_TOTAL, 256>>>(xyz1, xyz2, points2, t_embed,
                                 w_t1, b_t1, w_c1, b_c1,
                                 w_t2, b_t2, w_c2, b_c2);

    // 2. interpolation
    interp_kernel<<<dim3(NN/32, BB), 256>>>();

    // 3. Layer 1: y1h = fp16(w_c1 @ [points1; itph] + bias1), stats -> sum1/sq1
    gemm_f16<CIN, false><<<dim3(NN/64, BB), 256>>>(
        p_w1i, points1, p_itph, p_y1h, p_bias1,
        nullptr, nullptr, nullptr, nullptr, p_sum1, p_sq1);

    // 4. Layer 2: y2h = fp16(w_c2 @ gelu(bn1(y1h)) + bias2); BN1 finalized in-kernel
    gemm_f16<CO, true><<<dim3(NN/64, BB), 256>>>(
        p_w2i, (const float*)nullptr, p_y1h, p_y2h, p_bias2,
        p_sum1, p_sq1, g1, be1, p_sum2, p_sq2);

    // 5. final: BN2 finalize + gelu -> fp32 out
    final_kernel<<<(unsigned)(((size_t)BB*CO*NN/8 + 255)/256), 256>>>(
        p_y2h, p_sum2, p_sq2, g2, be2, out);
}

// round 13
// speedup vs baseline: 1.2606x; 1.0351x over previous
#include <cuda_runtime.h>
#include <cuda_fp16.h>
#include <math.h>
#include <stdint.h>

#define BB   8
#define NN   8192
#define SS   2048
#define C1c  128
#define C2c  256
#define CIN  384
#define TT   256
#define CO   256
#define COUNT_BN (BB*NN)

// ---------------- scratch (device globals) ----------------
__device__ float  d_p2t[BB*SS*C2c];                 // points2 transposed (B,S,C2)
__device__ int    d_idx3[BB*NN*3];
__device__ float  d_w3[BB*NN*3];
__device__ __half d_itph[(size_t)BB*C2c*NN];        // interpolated channels, fp16
__device__ __half d_y1h[(size_t)BB*CO*NN];          // layer1 output, fp16
__device__ __half d_y2h[(size_t)BB*CO*NN];          // layer2 raw output, fp16
__device__ float  d_bias1[BB*CO];
__device__ float  d_bias2[BB*CO];
__device__ float  d_sum1[CO], d_sq1[CO], d_sum2[CO], d_sq2[CO];
// fp16 A images in m16n8k16 fragment order
__device__ __half d_w1img[CO*CIN];
__device__ __half d_w2img[CO*CO];

// mega-kernel block ranges
#define MB_TOP3   256                    // (NN/256)*BB = 32*8
#define MB_TRANS  4096                   // 64*8*BB
#define MB_PERM1  384                    // CO*CIN/256
#define MB_PERM2  256                    // CO*CO/256
#define MB_BIAS   BB
#define MB_TOTAL  (MB_TOP3 + MB_TRANS + MB_PERM1 + MB_PERM2 + MB_BIAS)   // 5000

__device__ __forceinline__ float gelu_exact(float x) {
    return 0.5f * x * (1.0f + erff(x * 0.7071067811865476f));
}
__device__ __forceinline__ uint32_t smem_u32(const void* p) {
    uint32_t a;
    asm("{ .reg .u64 tmp; cvta.to.shared.u64 tmp, %1; cvt.u32.u64 %0, tmp; }" : "=r"(a) : "l"(p));
    return a;
}
__device__ __forceinline__ void cp16(uint32_t dst, const void* src) {
    asm volatile("cp.async.cg.shared.global [%0], [%1], 16;" :: "r"(dst), "l"(src));
}
__device__ __forceinline__ void cp_commit() { asm volatile("cp.async.commit_group;" ::: "memory"); }
__device__ __forceinline__ void cp_wait0()  { asm volatile("cp.async.wait_group 0;" ::: "memory"); }

#define MMA_F16(d, a, b0, b1)                                                     \
    asm volatile("mma.sync.aligned.m16n8k16.row.col.f32.f16.f16.f32 "             \
                 "{%0,%1,%2,%3}, {%4,%5,%6,%7}, {%8,%9}, {%0,%1,%2,%3};"          \
                 : "+f"(d[0]), "+f"(d[1]), "+f"(d[2]), "+f"(d[3])                 \
                 : "r"(a.x), "r"(a.y), "r"(a.z), "r"(a.w), "r"(b0), "r"(b1))

// ---------------- weight permute body (fp16 m16n8k16 fragment order) ----------------
__device__ __forceinline__ void permA16_body(const float* __restrict__ w,
                                             __half* __restrict__ img, int K, int idx)
{
    int o = idx / K, k = idx % K;
    int bm = o >> 4, r = o & 15;
    int g = r & 7, hi = r >> 3;
    int kt = k >> 5, kl = k & 31;
    int bk = kl >> 4, kk = kl & 15;
    int tq  = (kk & 7) >> 1;
    int khi = kk >> 3;
    int klo = kk & 1;
    int lane = g*4 + tq;
    int reg  = hi + 2*khi;
    size_t uidx = ((size_t)(kt*16 + bm)*2 + bk)*128 + lane*4 + reg;
    img[uidx*2 + klo] = __float2half_rn(w[idx]);
}

// ---------------- mega: top3 + transpose + weight perms + t-cond biases + stat zero ----------------
__global__ void __launch_bounds__(256) mega_prep(
    const float* __restrict__ xyz1, const float* __restrict__ xyz2,
    const float* __restrict__ points2, const float* __restrict__ t_embed,
    const float* __restrict__ w_t1, const float* __restrict__ b_t1,
    const float* __restrict__ w_c1, const float* __restrict__ b_c1,
    const float* __restrict__ w_t2, const float* __restrict__ b_t2,
    const float* __restrict__ w_c2, const float* __restrict__ b_c2)
{
    __shared__ __align__(16) char smem_raw[32768];
    int blk = blockIdx.x, t = threadIdx.x;

    if (blk < MB_TOP3) {
        // ---- 3-NN top3 (1 point/thread, e-form, float4 smem) ----
        float4* sq = (float4*)smem_raw;           // SS entries = 32KB
        int b = blk >> 5;
        int nblk = blk & 31;
        const float* x2 = xyz2 + (size_t)b*SS*3;
        for (int i = t; i < SS; i += 256) {
            float a = x2[i*3+0], bb = x2[i*3+1], c = x2[i*3+2];
            float4 q;
            q.x = -2.0f*a; q.y = -2.0f*bb; q.z = -2.0f*c;
            q.w = a*a + bb*bb + c*c;
            sq[i] = q;
        }
        __syncthreads();
        int n = nblk * 256 + t;
        const float* p = xyz1 + ((size_t)b*NN + n)*3;
        float px = p[0], py = p[1], pz = p[2];
        float n1 = px*px + py*py + pz*pz;
        float e0 = 3.4e38f, e1 = 3.4e38f, e2 = 3.4e38f;
        int   i0 = 0, i1 = 0, i2 = 0;
        #pragma unroll 4
        for (int s = 0; s < SS; s++) {
            float4 q = sq[s];
            float e = fmaf(px, q.x, fmaf(py, q.y, fmaf(pz, q.z, q.w)));
            if (e < e2) {
                e2 = e; i2 = s;
                if (e2 < e1) {
                    float te = e1; e1 = e2; e2 = te;
                    int   ti = i1; i1 = i2; i2 = ti;
                    if (e1 < e0) {
                        te = e0; e0 = e1; e1 = te;
                        ti = i0; i0 = i1; i1 = ti;
                    }
                }
            }
        }
        float d0 = n1 + e0, d1 = n1 + e1, d2 = n1 + e2;
        float r0 = 1.f/(d0 + 1e-8f), r1 = 1.f/(d1 + 1e-8f), r2 = 1.f/(d2 + 1e-8f);
        float inv = 1.f/(r0 + r1 + r2);
        size_t base = ((size_t)b*NN + n)*3;
        d_idx3[base+0] = i0; d_idx3[base+1] = i1; d_idx3[base+2] = i2;
        d_w3[base+0] = r0*inv; d_w3[base+1] = r1*inv; d_w3[base+2] = r2*inv;
    } else if (blk < MB_TOP3 + MB_TRANS) {
        // ---- points2 transpose (B,C2,S) -> (B,S,C2) ----
        typedef float Tile[33];
        Tile* tile = (Tile*)smem_raw;
        int tb = blk - MB_TOP3;
        int b  = tb >> 9;
        int r  = tb & 511;
        int s0 = (r & 63) * 32;
        int c0 = (r >> 6) * 32;
        int tx = t & 31, ty = t >> 5;   // 32 x 8
        const float* src = points2 + (size_t)b*C2c*SS;
        float*       dst = d_p2t   + (size_t)b*SS*C2c;
        #pragma unroll
        for (int j = 0; j < 32; j += 8)
            tile[ty+j][tx] = src[(size_t)(c0+ty+j)*SS + s0 + tx];
        __syncthreads();
        #pragma unroll
        for (int j = 0; j < 32; j += 8)
            dst[(size_t)(s0+ty+j)*C2c + c0 + tx] = tile[tx][ty+j];
    } else if (blk < MB_TOP3 + MB_TRANS + MB_PERM1) {
        int idx = (blk - MB_TOP3 - MB_TRANS)*256 + t;
        permA16_body(w_c1, d_w1img, CIN, idx);
    } else if (blk < MB_TOP3 + MB_TRANS + MB_PERM1 + MB_PERM2) {
        int idx = (blk - MB_TOP3 - MB_TRANS - MB_PERM1)*256 + t;
        permA16_body(w_c2, d_w2img, CO, idx);
    } else {
        // ---- t-cond bias folding (256 threads) + stat zero ----
        float* g   = (float*)smem_raw;          // 256
        float* te1 = g + TT;                    // 384
        float* te2 = te1 + CIN;                 // 256
        int b = blk - (MB_TOP3 + MB_TRANS + MB_PERM1 + MB_PERM2);
        g[t] = gelu_exact(t_embed[b*TT + t]);
        __syncthreads();
        for (int c = t; c < CIN; c += 256) {
            float s = b_t1[c];
            const float* w = w_t1 + (size_t)c*TT;
            #pragma unroll 8
            for (int k = 0; k < TT; k++) s = fmaf(g[k], w[k], s);
            te1[c] = s;
        }
        {
            float s = b_t2[t];
            const float* w = w_t2 + (size_t)t*TT;
            #pragma unroll 8
            for (int k = 0; k < TT; k++) s = fmaf(g[k], w[k], s);
            te2[t] = s;
        }
        __syncthreads();
        {
            float s1 = b_c1[t];
            const float* w1 = w_c1 + (size_t)t*CIN;
            #pragma unroll 8
            for (int k = 0; k < CIN; k++) s1 = fmaf(te1[k], w1[k], s1);
            d_bias1[b*CO + t] = s1;
            float s2 = b_c2[t];
            const float* w2 = w_c2 + (size_t)t*CO;
            #pragma unroll 8
            for (int k = 0; k < CO; k++) s2 = fmaf(te2[k], w2[k], s2);
            d_bias2[b*CO + t] = s2;
        }
        if (b == 0) {
            d_sum1[t] = 0.f; d_sq1[t] = 0.f; d_sum2[t] = 0.f; d_sq2[t] = 0.f;
        }
    }
}

// ---------------- 3-NN interpolation into d_itph, float4 gather ----------------
// 256 threads = 64 channel-quads x 4 point-groups. Thread (q, pg) loads float4
// (channels 4q..4q+3) from each neighbor row of its point -> 24 LDG.128 total.
__global__ void __launch_bounds__(256) interp_kernel()
{
    __shared__ __half sc[C2c][34];
    __shared__ int    sidx[32*3];
    __shared__ float  swt[32*3];
    int b  = blockIdx.y;
    int n0 = blockIdx.x * 32;
    int t  = threadIdx.x;
    if (t < 96) {
        size_t base = ((size_t)b*NN + n0)*3;
        sidx[t] = d_idx3[base + t];
        swt[t]  = d_w3[base + t];
    }
    __syncthreads();
    const float* p2t = d_p2t + (size_t)b*SS*C2c;
    int q  = t & 63;          // channel quad
    int pg = t >> 6;          // point group (0..3)
    int c0 = q * 4;
    #pragma unroll
    for (int p = 0; p < 8; p++) {
        int nl = pg + p*4;    // point 0..31
        int   j0 = sidx[nl*3+0], j1 = sidx[nl*3+1], j2 = sidx[nl*3+2];
        float w0 = swt[nl*3+0],  w1 = swt[nl*3+1],  w2 = swt[nl*3+2];
        float4 v0 = *(const float4*)(p2t + (size_t)j0*C2c + c0);
        float4 v1 = *(const float4*)(p2t + (size_t)j1*C2c + c0);
        float4 v2 = *(const float4*)(p2t + (size_t)j2*C2c + c0);
        float r0 = fmaf(w2, v2.x, fmaf(w1, v1.x, w0*v0.x));
        float r1 = fmaf(w2, v2.y, fmaf(w1, v1.y, w0*v0.y));
        float r2 = fmaf(w2, v2.z, fmaf(w1, v1.z, w0*v0.z));
        float r3 = fmaf(w2, v2.w, fmaf(w1, v1.w, w0*v0.w));
        sc[c0+0][nl] = __float2half_rn(r0);
        sc[c0+1][nl] = __float2half_rn(r1);
        sc[c0+2][nl] = __float2half_rn(r2);
        sc[c0+3][nl] = __float2half_rn(r3);
    }
    __syncthreads();
    __half* xout = d_itph + (size_t)b*C2c*NN + n0;
    int nl2 = (t & 15) * 2;
    int cc0 = t >> 4;
    #pragma unroll
    for (int c = cc0; c < C2c; c += 16) {
        __half2 hv;
        hv.x = sc[c][nl2];
        hv.y = sc[c][nl2 + 1];
        *(__half2*)(xout + (size_t)c*NN + nl2) = hv;
    }
}

// ---------------- fp16 tensor-core GEMM (R12 verbatim) ----------------
template<int KTOT, bool L2MODE>
__global__ void __launch_bounds__(256) gemm_f16(
    const __half* __restrict__ AimgH,
    const float* __restrict__ Xp1,
    const __half* __restrict__ Xh,
    __half* __restrict__ Yh,
    const float* __restrict__ bias,
    const float* __restrict__ sumIn, const float* __restrict__ sqIn,
    const float* __restrict__ gamma, const float* __restrict__ beta,
    float* __restrict__ sumOut, float* __restrict__ sqOut)
{
    constexpr int NC = KTOT / 32;
    __shared__ __align__(16) uint4    As[2][1024];
    __shared__ __align__(16) uint32_t Bs[2][1024];
    __shared__ float redS[CO], redQ[CO];
    __shared__ float sA[CO], sB[CO];

    const uint32_t* Aimg = (const uint32_t*)AimgH;
    int t = threadIdx.x, l = t & 31, w = t >> 5;
    int wm = w >> 1, wn = w & 1;
    int g = l >> 2, tq = l & 3;
    int b = blockIdx.y, nT = blockIdx.x * 64;

    redS[t] = 0.f; redQ[t] = 0.f;
    if (L2MODE) {
        float m = sumIn[t] * (1.0f/COUNT_BN);
        float v = sqIn[t]  * (1.0f/COUNT_BN) - m*m;
        float inv = rsqrtf(v + 1e-5f);
        float a = gamma[t] * inv;
        sA[t] = a;
        sB[t] = beta[t] - a*m;
    }
    __syncthreads();

    int kp = t >> 4, n4 = t & 15;

    float acc[4][4][4];
    #pragma unroll
    for (int i = 0; i < 4; i++)
        #pragma unroll
        for (int j = 0; j < 4; j++)
            #pragma unroll
            for (int r = 0; r < 4; r++) acc[i][j][r] = 0.f;

    float pv[8];
    auto stageB = [&](int c) {
        int k0 = c*32 + 2*kp;
        bool useH = L2MODE || (k0 >= C1c);
        if (useH) {
            int kk = L2MODE ? k0 : (k0 - C1c);
            const __half* bh = Xh + (size_t)b*C2c*NN + (size_t)kk*NN + nT + 4*n4;
            uint2 u0 = *(const uint2*)bh;
            uint2 u1 = *(const uint2*)(bh + NN);
            __half2 h;
            h = *(__half2*)&u0.x; pv[0] = __low2float(h); pv[1] = __high2float(h);
            h = *(__half2*)&u0.y; pv[2] = __low2float(h); pv[3] = __high2float(h);
            h = *(__half2*)&u1.x; pv[4] = __low2float(h); pv[5] = __high2float(h);
            h = *(__half2*)&u1.y; pv[6] = __low2float(h); pv[7] = __high2float(h);
        } else {
            const float* base = Xp1 + (size_t)b*C1c*NN + (size_t)k0*NN + nT + 4*n4;
            float4 v0 = *(const float4*)base;
            float4 v1 = *(const float4*)(base + NN);
            pv[0] = v0.x; pv[1] = v0.y; pv[2] = v0.z; pv[3] = v0.w;
            pv[4] = v1.x; pv[5] = v1.y; pv[6] = v1.z; pv[7] = v1.w;
        }
    };
    auto storeB = [&](int c, int buf) {
        float f[8];
        #pragma unroll
        for (int j = 0; j < 8; j++) f[j] = pv[j];
        if (L2MODE) {
            int kg0 = c*32 + 2*kp;
            float a0 = sA[kg0],   b0 = sB[kg0];
            float a1 = sA[kg0+1], b1 = sB[kg0+1];
            #pragma unroll
            for (int j = 0; j < 4; j++) f[j]   = gelu_exact(fmaf(a0, f[j],   b0));
            #pragma unroll
            for (int j = 0; j < 4; j++) f[j+4] = gelu_exact(fmaf(a1, f[j+4], b1));
        }
        uint4 u;
        __half2 h;
        h = __floats2half2_rn(f[0], f[4]); u.x = *(uint32_t*)&h;
        h = __floats2half2_rn(f[1], f[5]); u.y = *(uint32_t*)&h;
        h = __floats2half2_rn(f[2], f[6]); u.z = *(uint32_t*)&h;
        h = __floats2half2_rn(f[3], f[7]); u.w = *(uint32_t*)&h;
        ((uint4*)Bs[buf])[kp*16 + (n4 ^ ((kp & 3) << 1))] = u;
    };
    auto stageA = [&](int c, int buf) {
        const uint32_t* src = Aimg + (size_t)c*4096 + t*4;
        uint32_t base = smem_u32(&As[buf][0]);
        #pragma unroll
        for (int j = 0; j < 4; j++)
            cp16(base + (uint32_t)(t + j*256)*16u, src + j*1024);
    };
    auto compute = [&](int buf) {
        uint4 af[4][2];
        #pragma unroll
        for (int mf = 0; mf < 4; mf++)
            #pragma unroll
            for (int bk = 0; bk < 2; bk++)
                af[mf][bk] = As[buf][((wm*4 + mf)*2 + bk)*32 + l];
        uint32_t bf[4][2][2];
        #pragma unroll
        for (int bnl = 0; bnl < 4; bnl++) {
            int n = wn*32 + bnl*8 + g;
            int nsw = n ^ (tq << 3);
            #pragma unroll
            for (int bk = 0; bk < 2; bk++) {
                bf[bnl][bk][0] = Bs[buf][(bk*8 + tq)*64 + nsw];
                bf[bnl][bk][1] = Bs[buf][(bk*8 + tq + 4)*64 + nsw];
            }
        }
        #pragma unroll
        for (int mf = 0; mf < 4; mf++)
            #pragma unroll
            for (int bnl = 0; bnl < 4; bnl++)
                #pragma unroll
                for (int bk = 0; bk < 2; bk++)
                    MMA_F16(acc[mf][bnl], af[mf][bk], bf[bnl][bk][0], bf[bnl][bk][1]);
    };

    stageB(0);
    stageA(0, 0); cp_commit();
    storeB(0, 0);
    for (int c = 0; c < NC; c++) {
        int buf = c & 1;
        cp_wait0();
        __syncthreads();
        if (c + 1 < NC) { stageB(c + 1); stageA(c + 1, buf ^ 1); cp_commit(); }
        compute(buf);
        if (c + 1 < NC) storeB(c + 1, buf ^ 1);
    }

    #pragma unroll
    for (int mf = 0; mf < 4; mf++) {
        int o_lo = wm*64 + mf*16 + g;
        int o_hi = o_lo + 8;
        float bl = bias[b*CO + o_lo];
        float bh = bias[b*CO + o_hi];
        float sl = 0.f, ql = 0.f, sh = 0.f, qh = 0.f;
        #pragma unroll
        for (int bnl = 0; bnl < 4; bnl++) {
            int col = nT + wn*32 + bnl*8 + 2*tq;
            float v0 = acc[mf][bnl][0] + bl;
            float v1 = acc[mf][bnl][1] + bl;
            float v2 = acc[mf][bnl][2] + bh;
            float v3 = acc[mf][bnl][3] + bh;
            __half2 hlo = __floats2half2_rn(v0, v1);
            __half2 hhi = __floats2half2_rn(v2, v3);
            *(__half2*)(Yh + (size_t)b*CO*NN + (size_t)o_lo*NN + col) = hlo;
            *(__half2*)(Yh + (size_t)b*CO*NN + (size_t)o_hi*NN + col) = hhi;
            sl += v0 + v1; ql += v0*v0 + v1*v1;
            sh += v2 + v3; qh += v2*v2 + v3*v3;
        }
        #pragma unroll
        for (int off = 1; off <= 2; off <<= 1) {
            sl += __shfl_xor_sync(0xffffffffu, sl, off);
            ql += __shfl_xor_sync(0xffffffffu, ql, off);
            sh += __shfl_xor_sync(0xffffffffu, sh, off);
            qh += __shfl_xor_sync(0xffffffffu, qh, off);
        }
        if (tq == 0) {
            atomicAdd(&redS[o_lo], sl);
            atomicAdd(&redQ[o_lo], ql);
            atomicAdd(&redS[o_hi], sh);
            atomicAdd(&redQ[o_hi], qh);
        }
    }
    __syncthreads();
    atomicAdd(&sumOut[t], redS[t]);
    atomicAdd(&sqOut[t],  redQ[t]);
}

// ---------------- final: BN2 finalize + gelu in one pass, fp16 -> fp32 ----------------
__global__ void __launch_bounds__(256) final_kernel(
    const __half* __restrict__ y2h,
    const float* __restrict__ sum2, const float* __restrict__ sq2,
    const float* __restrict__ gamma, const float* __restrict__ beta,
    float* __restrict__ out)
{
    size_t i8 = (size_t)blockIdx.x * 256 + threadIdx.x;
    size_t total8 = (size_t)BB*CO*NN/8;
    if (i8 >= total8) return;
    uint4 u = ((const uint4*)y2h)[i8];
    size_t i = i8 * 8;
    int c = (int)((i >> 13) & 255);
    float m = sum2[c] * (1.0f/COUNT_BN);
    float v = sq2[c]  * (1.0f/COUNT_BN) - m*m;
    float inv = rsqrtf(v + 1e-5f);
    float a = gamma[c] * inv;
    float bo = beta[c] - a*m;
    const __half2* hp = (const __half2*)&u;
    float4 o0, o1;
    float2 f;
    f = __half22float2(hp[0]); o0.x = gelu_exact(fmaf(a, f.x, bo)); o0.y = gelu_exact(fmaf(a, f.y, bo));
    f = __half22float2(hp[1]); o0.z = gelu_exact(fmaf(a, f.x, bo)); o0.w = gelu_exact(fmaf(a, f.y, bo));
    f = __half22float2(hp[2]); o1.x = gelu_exact(fmaf(a, f.x, bo)); o1.y = gelu_exact(fmaf(a, f.y, bo));
    f = __half22float2(hp[3]); o1.z = gelu_exact(fmaf(a, f.x, bo)); o1.w = gelu_exact(fmaf(a, f.y, bo));
    ((float4*)out)[i8*2 + 0] = o0;
    ((float4*)out)[i8*2 + 1] = o1;
}

// ---------------- launch ----------------
extern "C" void kernel_launch(void* const* d_in, const int* in_sizes, int n_in,
                              void* d_out, int out_size)
{
    const float* xyz1    = (const float*)d_in[0];
    const float* xyz2    = (const float*)d_in[1];
    const float* points1 = (const float*)d_in[2];
    const float* points2 = (const float*)d_in[3];
    const float* t_embed = (const float*)d_in[4];
    const float* w_t1 = (const float*)d_in[5];
    const float* b_t1 = (const float*)d_in[6];
    const float* w_c1 = (const float*)d_in[7];
    const float* b_c1 = (const float*)d_in[8];
    const float* g1   = (const float*)d_in[9];
    const float* be1  = (const float*)d_in[10];
    const float* w_t2 = (const float*)d_in[11];
    const float* b_t2 = (const float*)d_in[12];
    const float* w_c2 = (const float*)d_in[13];
    const float* b_c2 = (const float*)d_in[14];
    const float* g2   = (const float*)d_in[15];
    const float* be2  = (const float*)d_in[16];
    float* out = (float*)d_out;

    float *p_bias1, *p_bias2;
    float *p_sum1, *p_sq1, *p_sum2, *p_sq2;
    __half *p_itph, *p_y1h, *p_y2h, *p_w1i, *p_w2i;
    cudaGetSymbolAddress((void**)&p_itph,  d_itph);
    cudaGetSymbolAddress((void**)&p_y1h,   d_y1h);
    cudaGetSymbolAddress((void**)&p_y2h,   d_y2h);
    cudaGetSymbolAddress((void**)&p_bias1, d_bias1);
    cudaGetSymbolAddress((void**)&p_bias2, d_bias2);
    cudaGetSymbolAddress((void**)&p_sum1,  d_sum1);
    cudaGetSymbolAddress((void**)&p_sq1,   d_sq1);
    cudaGetSymbolAddress((void**)&p_sum2,  d_sum2);
    cudaGetSymbolAddress((void**)&p_sq2,   d_sq2);
    cudaGetSymbolAddress((void**)&p_w1i,   d_w1img);
    cudaGetSymbolAddress((void**)&p_w2i,   d_w2img);

    // 1. mega-prep: top3 + transpose + weight perms + biases + stat zero
    mega_prep<<<MB_TOTAL, 256>>>(xyz1, xyz2, points2, t_embed,
                                 w_t1, b_t1, w_c1, b_c1,
                                 w_t2, b_t2, w_c2, b_c2);

    // 2. interpolation (float4 gather)
    interp_kernel<<<dim3(NN/32, BB), 256>>>();

    // 3. Layer 1: y1h = fp16(w_c1 @ [points1; itph] + bias1), stats -> sum1/sq1
    gemm_f16<CIN, false><<<dim3(NN/64, BB), 256>>>(
        p_w1i, points1, p_itph, p_y1h, p_bias1,
        nullptr, nullptr, nullptr, nullptr, p_sum1, p_sq1);

    // 4. Layer 2: y2h = fp16(w_c2 @ gelu(bn1(y1h)) + bias2); BN1 finalized in-kernel
    gemm_f16<CO, true><<<dim3(NN/64, BB), 256>>>(
        p_w2i, (const float*)nullptr, p_y1h, p_y2h, p_bias2,
        p_sum1, p_sq1, g1, be1, p_sum2, p_sq2);

    // 5. final: BN2 finalize + gelu -> fp32 out
    final_kernel<<<(unsigned)(((size_t)BB*CO*NN/8 + 255)/256), 256>>>(
        p_y2h, p_sum2, p_sq2, g2, be2, out);
}

// round 15
// speedup vs baseline: 1.2924x; 1.0252x over previous
#include <cuda_runtime.h>
#include <cuda_fp16.h>
#include <math.h>
#include <stdint.h>

#define BB   8
#define NN   8192
#define SS   2048
#define C1c  128
#define C2c  256
#define CIN  384
#define TT   256
#define CO   256
#define COUNT_BN (BB*NN)

// ---------------- scratch (device globals) ----------------
__device__ float  d_p2t[BB*SS*C2c];                 // points2 transposed (B,S,C2)
__device__ int    d_idx3[BB*NN*3];
__device__ float  d_w3[BB*NN*3];
__device__ __half d_itph[(size_t)BB*C2c*NN];        // interpolated channels, fp16
__device__ __half d_y1h[(size_t)BB*CO*NN];          // layer1 output, fp16
__device__ __half d_y2h[(size_t)BB*CO*NN];          // layer2 raw output, fp16
__device__ float  d_bias1[BB*CO];
__device__ float  d_bias2[BB*CO];
__device__ float  d_sum1[CO], d_sq1[CO], d_sum2[CO], d_sq2[CO];
// fp16 A images in m16n8k16 fragment order
__device__ __half d_w1img[CO*CIN];
__device__ __half d_w2img[CO*CO];

// mega-kernel block ranges
#define MB_TOP3   256                    // (NN/256)*BB = 32*8
#define MB_TRANS  4096                   // 64*8*BB
#define MB_PERM1  384                    // CO*CIN/256
#define MB_PERM2  256                    // CO*CO/256
#define MB_BIAS   BB
#define MB_TOTAL  (MB_TOP3 + MB_TRANS + MB_PERM1 + MB_PERM2 + MB_BIAS)   // 5000

__device__ __forceinline__ float gelu_exact(float x) {
    return 0.5f * x * (1.0f + erff(x * 0.7071067811865476f));
}
__device__ __forceinline__ uint32_t smem_u32(const void* p) {
    uint32_t a;
    asm("{ .reg .u64 tmp; cvta.to.shared.u64 tmp, %1; cvt.u32.u64 %0, tmp; }" : "=r"(a) : "l"(p));
    return a;
}
__device__ __forceinline__ void cp16(uint32_t dst, const void* src) {
    asm volatile("cp.async.cg.shared.global [%0], [%1], 16;" :: "r"(dst), "l"(src));
}
__device__ __forceinline__ void cp_commit() { asm volatile("cp.async.commit_group;" ::: "memory"); }
__device__ __forceinline__ void cp_wait0()  { asm volatile("cp.async.wait_group 0;" ::: "memory"); }

#define MMA_F16(d, a, b0, b1)                                                     \
    asm volatile("mma.sync.aligned.m16n8k16.row.col.f32.f16.f16.f32 "             \
                 "{%0,%1,%2,%3}, {%4,%5,%6,%7}, {%8,%9}, {%0,%1,%2,%3};"          \
                 : "+f"(d[0]), "+f"(d[1]), "+f"(d[2]), "+f"(d[3])                 \
                 : "r"(a.x), "r"(a.y), "r"(a.z), "r"(a.w), "r"(b0), "r"(b1))

// ---------------- weight permute body (fp16 m16n8k16 fragment order) ----------------
__device__ __forceinline__ void permA16_body(const float* __restrict__ w,
                                             __half* __restrict__ img, int K, int idx)
{
    int o = idx / K, k = idx % K;
    int bm = o >> 4, r = o & 15;
    int g = r & 7, hi = r >> 3;
    int kt = k >> 5, kl = k & 31;
    int bk = kl >> 4, kk = kl & 15;
    int tq  = (kk & 7) >> 1;
    int khi = kk >> 3;
    int klo = kk & 1;
    int lane = g*4 + tq;
    int reg  = hi + 2*khi;
    size_t uidx = ((size_t)(kt*16 + bm)*2 + bk)*128 + lane*4 + reg;
    img[uidx*2 + klo] = __float2half_rn(w[idx]);
}

// ---------------- mega: top3 + transpose + weight perms + t-cond biases + stat zero ----------------
__global__ void __launch_bounds__(256) mega_prep(
    const float* __restrict__ xyz1, const float* __restrict__ xyz2,
    const float* __restrict__ points2, const float* __restrict__ t_embed,
    const float* __restrict__ w_t1, const float* __restrict__ b_t1,
    const float* __restrict__ w_c1, const float* __restrict__ b_c1,
    const float* __restrict__ w_t2, const float* __restrict__ b_t2,
    const float* __restrict__ w_c2, const float* __restrict__ b_c2)
{
    __shared__ __align__(16) char smem_raw[32768];
    int blk = blockIdx.x, t = threadIdx.x;

    if (blk < MB_TOP3) {
        // ---- 3-NN top3 (1 point/thread, e-form, float4 smem) ----
        float4* sq = (float4*)smem_raw;           // SS entries = 32KB
        int b = blk >> 5;
        int nblk = blk & 31;
        const float* x2 = xyz2 + (size_t)b*SS*3;
        for (int i = t; i < SS; i += 256) {
            float a = x2[i*3+0], bb = x2[i*3+1], c = x2[i*3+2];
            float4 q;
            q.x = -2.0f*a; q.y = -2.0f*bb; q.z = -2.0f*c;
            q.w = a*a + bb*bb + c*c;
            sq[i] = q;
        }
        __syncthreads();
        int n = nblk * 256 + t;
        const float* p = xyz1 + ((size_t)b*NN + n)*3;
        float px = p[0], py = p[1], pz = p[2];
        float n1 = px*px + py*py + pz*pz;
        float e0 = 3.4e38f, e1 = 3.4e38f, e2 = 3.4e38f;
        int   i0 = 0, i1 = 0, i2 = 0;
        #pragma unroll 4
        for (int s = 0; s < SS; s++) {
            float4 q = sq[s];
            float e = fmaf(px, q.x, fmaf(py, q.y, fmaf(pz, q.z, q.w)));
            if (e < e2) {
                e2 = e; i2 = s;
                if (e2 < e1) {
                    float te = e1; e1 = e2; e2 = te;
                    int   ti = i1; i1 = i2; i2 = ti;
                    if (e1 < e0) {
                        te = e0; e0 = e1; e1 = te;
                        ti = i0; i0 = i1; i1 = ti;
                    }
                }
            }
        }
        float d0 = n1 + e0, d1 = n1 + e1, d2 = n1 + e2;
        float r0 = 1.f/(d0 + 1e-8f), r1 = 1.f/(d1 + 1e-8f), r2 = 1.f/(d2 + 1e-8f);
        float inv = 1.f/(r0 + r1 + r2);
        size_t base = ((size_t)b*NN + n)*3;
        d_idx3[base+0] = i0; d_idx3[base+1] = i1; d_idx3[base+2] = i2;
        d_w3[base+0] = r0*inv; d_w3[base+1] = r1*inv; d_w3[base+2] = r2*inv;
    } else if (blk < MB_TOP3 + MB_TRANS) {
        // ---- points2 transpose (B,C2,S) -> (B,S,C2) ----
        typedef float Tile[33];
        Tile* tile = (Tile*)smem_raw;
        int tb = blk - MB_TOP3;
        int b  = tb >> 9;
        int r  = tb & 511;
        int s0 = (r & 63) * 32;
        int c0 = (r >> 6) * 32;
        int tx = t & 31, ty = t >> 5;   // 32 x 8
        const float* src = points2 + (size_t)b*C2c*SS;
        float*       dst = d_p2t   + (size_t)b*SS*C2c;
        #pragma unroll
        for (int j = 0; j < 32; j += 8)
            tile[ty+j][tx] = src[(size_t)(c0+ty+j)*SS + s0 + tx];
        __syncthreads();
        #pragma unroll
        for (int j = 0; j < 32; j += 8)
            dst[(size_t)(s0+ty+j)*C2c + c0 + tx] = tile[tx][ty+j];
    } else if (blk < MB_TOP3 + MB_TRANS + MB_PERM1) {
        int idx = (blk - MB_TOP3 - MB_TRANS)*256 + t;
        permA16_body(w_c1, d_w1img, CIN, idx);
    } else if (blk < MB_TOP3 + MB_TRANS + MB_PERM1 + MB_PERM2) {
        int idx = (blk - MB_TOP3 - MB_TRANS - MB_PERM1)*256 + t;
        permA16_body(w_c2, d_w2img, CO, idx);
    } else {
        // ---- t-cond bias folding (256 threads) + stat zero ----
        float* g   = (float*)smem_raw;          // 256
        float* te1 = g + TT;                    // 384
        float* te2 = te1 + CIN;                 // 256
        int b = blk - (MB_TOP3 + MB_TRANS + MB_PERM1 + MB_PERM2);
        g[t] = gelu_exact(t_embed[b*TT + t]);
        __syncthreads();
        for (int c = t; c < CIN; c += 256) {
            float s = b_t1[c];
            const float* w = w_t1 + (size_t)c*TT;
            #pragma unroll 8
            for (int k = 0; k < TT; k++) s = fmaf(g[k], w[k], s);
            te1[c] = s;
        }
        {
            float s = b_t2[t];
            const float* w = w_t2 + (size_t)t*TT;
            #pragma unroll 8
            for (int k = 0; k < TT; k++) s = fmaf(g[k], w[k], s);
            te2[t] = s;
        }
        __syncthreads();
        {
            float s1 = b_c1[t];
            const float* w1 = w_c1 + (size_t)t*CIN;
            #pragma unroll 8
            for (int k = 0; k < CIN; k++) s1 = fmaf(te1[k], w1[k], s1);
            d_bias1[b*CO + t] = s1;
            float s2 = b_c2[t];
            const float* w2 = w_c2 + (size_t)t*CO;
            #pragma unroll 8
            for (int k = 0; k < CO; k++) s2 = fmaf(te2[k], w2[k], s2);
            d_bias2[b*CO + t] = s2;
        }
        if (b == 0) {
            d_sum1[t] = 0.f; d_sq1[t] = 0.f; d_sum2[t] = 0.f; d_sq2[t] = 0.f;
        }
    }
}

// ---------------- 3-NN interpolation into d_itph, float4 gather ----------------
__global__ void __launch_bounds__(256) interp_kernel()
{
    __shared__ __half sc[C2c][34];
    __shared__ int    sidx[32*3];
    __shared__ float  swt[32*3];
    int b  = blockIdx.y;
    int n0 = blockIdx.x * 32;
    int t  = threadIdx.x;
    if (t < 96) {
        size_t base = ((size_t)b*NN + n0)*3;
        sidx[t] = d_idx3[base + t];
        swt[t]  = d_w3[base + t];
    }
    __syncthreads();
    const float* p2t = d_p2t + (size_t)b*SS*C2c;
    int q  = t & 63;          // channel quad
    int pg = t >> 6;          // point group (0..3)
    int c0 = q * 4;
    #pragma unroll
    for (int p = 0; p < 8; p++) {
        int nl = pg + p*4;    // point 0..31
        int   j0 = sidx[nl*3+0], j1 = sidx[nl*3+1], j2 = sidx[nl*3+2];
        float w0 = swt[nl*3+0],  w1 = swt[nl*3+1],  w2 = swt[nl*3+2];
        float4 v0 = *(const float4*)(p2t + (size_t)j0*C2c + c0);
        float4 v1 = *(const float4*)(p2t + (size_t)j1*C2c + c0);
        float4 v2 = *(const float4*)(p2t + (size_t)j2*C2c + c0);
        float r0 = fmaf(w2, v2.x, fmaf(w1, v1.x, w0*v0.x));
        float r1 = fmaf(w2, v2.y, fmaf(w1, v1.y, w0*v0.y));
        float r2 = fmaf(w2, v2.z, fmaf(w1, v1.z, w0*v0.z));
        float r3 = fmaf(w2, v2.w, fmaf(w1, v1.w, w0*v0.w));
        sc[c0+0][nl] = __float2half_rn(r0);
        sc[c0+1][nl] = __float2half_rn(r1);
        sc[c0+2][nl] = __float2half_rn(r2);
        sc[c0+3][nl] = __float2half_rn(r3);
    }
    __syncthreads();
    __half* xout = d_itph + (size_t)b*C2c*NN + n0;
    int nl2 = (t & 15) * 2;
    int cc0 = t >> 4;
    #pragma unroll
    for (int c = cc0; c < C2c; c += 16) {
        __half2 hv;
        hv.x = sc[c][nl2];
        hv.y = sc[c][nl2 + 1];
        *(__half2*)(xout + (size_t)c*NN + nl2) = hv;
    }
}

// ---------------- fp16 tensor-core GEMM (R13 semantics + hoisted B addressing) ----------------
// Identical logical/physical mapping to R13: for warp-uniform logical bnl,
// each lane reads physical word tq*64 + wn*32 + ((bnl^tq)<<3) + g (+ bk/jj imms).
// The lane-dependent part is precomputed once (Doff[bnl]) instead of per chunk.
template<int KTOT, bool L2MODE>
__global__ void __launch_bounds__(256) gemm_f16(
    const __half* __restrict__ AimgH,
    const float* __restrict__ Xp1,
    const __half* __restrict__ Xh,
    __half* __restrict__ Yh,
    const float* __restrict__ bias,
    const float* __restrict__ sumIn, const float* __restrict__ sqIn,
    const float* __restrict__ gamma, const float* __restrict__ beta,
    float* __restrict__ sumOut, float* __restrict__ sqOut)
{
    constexpr int NC = KTOT / 32;
    __shared__ __align__(16) uint4    As[2][1024];
    __shared__ __align__(16) uint32_t Bs[2][1024];
    __shared__ float redS[CO], redQ[CO];
    __shared__ float sA[CO], sB[CO];

    const uint32_t* Aimg = (const uint32_t*)AimgH;
    int t = threadIdx.x, l = t & 31, w = t >> 5;
    int wm = w >> 1, wn = w & 1;
    int g = l >> 2, tq = l & 3;
    int b = blockIdx.y, nT = blockIdx.x * 64;

    redS[t] = 0.f; redQ[t] = 0.f;
    if (L2MODE) {
        float m = sumIn[t] * (1.0f/COUNT_BN);
        float v = sqIn[t]  * (1.0f/COUNT_BN) - m*m;
        float inv = rsqrtf(v + 1e-5f);
        float a = gamma[t] * inv;
        sA[t] = a;
        sB[t] = beta[t] - a*m;
    }
    __syncthreads();

    int kp = t >> 4, n4 = t & 15;

    // hoisted per-lane B-fragment word offsets (same values R13 computed per chunk)
    uint32_t Doff[4];
    #pragma unroll
    for (int bnl = 0; bnl < 4; bnl++)
        Doff[bnl] = (uint32_t)(tq*64 + wn*32 + ((bnl ^ tq) << 3) + g);

    float acc[4][4][4];
    #pragma unroll
    for (int i = 0; i < 4; i++)
        #pragma unroll
        for (int j = 0; j < 4; j++)
            #pragma unroll
            for (int r = 0; r < 4; r++) acc[i][j][r] = 0.f;

    float pv[8];
    auto stageB = [&](int c) {
        int k0 = c*32 + 2*kp;
        bool useH = L2MODE || (k0 >= C1c);
        if (useH) {
            int kk = L2MODE ? k0 : (k0 - C1c);
            const __half* bh = Xh + (size_t)b*C2c*NN + (size_t)kk*NN + nT + 4*n4;
            uint2 u0 = *(const uint2*)bh;
            uint2 u1 = *(const uint2*)(bh + NN);
            __half2 h;
            h = *(__half2*)&u0.x; pv[0] = __low2float(h); pv[1] = __high2float(h);
            h = *(__half2*)&u0.y; pv[2] = __low2float(h); pv[3] = __high2float(h);
            h = *(__half2*)&u1.x; pv[4] = __low2float(h); pv[5] = __high2float(h);
            h = *(__half2*)&u1.y; pv[6] = __low2float(h); pv[7] = __high2float(h);
        } else {
            const float* base = Xp1 + (size_t)b*C1c*NN + (size_t)k0*NN + nT + 4*n4;
            float4 v0 = *(const float4*)base;
            float4 v1 = *(const float4*)(base + NN);
            pv[0] = v0.x; pv[1] = v0.y; pv[2] = v0.z; pv[3] = v0.w;
            pv[4] = v1.x; pv[5] = v1.y; pv[6] = v1.z; pv[7] = v1.w;
        }
    };
    auto storeB = [&](int c, int buf) {
        float f[8];
        #pragma unroll
        for (int j = 0; j < 8; j++) f[j] = pv[j];
        if (L2MODE) {
            int kg0 = c*32 + 2*kp;
            float a0 = sA[kg0],   b0 = sB[kg0];
            float a1 = sA[kg0+1], b1 = sB[kg0+1];
            #pragma unroll
            for (int j = 0; j < 4; j++) f[j]   = gelu_exact(fmaf(a0, f[j],   b0));
            #pragma unroll
            for (int j = 0; j < 4; j++) f[j+4] = gelu_exact(fmaf(a1, f[j+4], b1));
        }
        uint4 u;
        __half2 h;
        h = __floats2half2_rn(f[0], f[4]); u.x = *(uint32_t*)&h;
        h = __floats2half2_rn(f[1], f[5]); u.y = *(uint32_t*)&h;
        h = __floats2half2_rn(f[2], f[6]); u.z = *(uint32_t*)&h;
        h = __floats2half2_rn(f[3], f[7]); u.w = *(uint32_t*)&h;
        ((uint4*)Bs[buf])[kp*16 + (n4 ^ ((kp & 3) << 1))] = u;
    };
    auto stageA = [&](int c, int buf) {
        const uint32_t* src = Aimg + (size_t)c*4096 + t*4;
        uint32_t base = smem_u32(&As[buf][0]);
        #pragma unroll
        for (int j = 0; j < 4; j++)
            cp16(base + (uint32_t)(t + j*256)*16u, src + j*1024);
    };
    auto compute = [&](int buf) {
        const uint32_t* bs = Bs[buf];
        uint4 af[4][2];
        #pragma unroll
        for (int mf = 0; mf < 4; mf++)
            #pragma unroll
            for (int bk = 0; bk < 2; bk++)
                af[mf][bk] = As[buf][((wm*4 + mf)*2 + bk)*32 + l];
        uint32_t bf[4][2][2];
        #pragma unroll
        for (int bnl = 0; bnl < 4; bnl++) {
            #pragma unroll
            for (int bk = 0; bk < 2; bk++) {
                bf[bnl][bk][0] = bs[Doff[bnl] + bk*512];
                bf[bnl][bk][1] = bs[Doff[bnl] + bk*512 + 256];
            }
        }
        #pragma unroll
        for (int mf = 0; mf < 4; mf++)
            #pragma unroll
            for (int bnl = 0; bnl < 4; bnl++)
                #pragma unroll
                for (int bk = 0; bk < 2; bk++)
                    MMA_F16(acc[mf][bnl], af[mf][bk], bf[bnl][bk][0], bf[bnl][bk][1]);
    };

    stageB(0);
    stageA(0, 0); cp_commit();
    storeB(0, 0);
    #pragma unroll 2
    for (int c = 0; c < NC; c++) {
        int buf = c & 1;
        cp_wait0();
        __syncthreads();
        if (c + 1 < NC) { stageB(c + 1); stageA(c + 1, buf ^ 1); cp_commit(); }
        compute(buf);
        if (c + 1 < NC) storeB(c + 1, buf ^ 1);
    }

    // ---- epilogue: bias, fp16 store, stats (R13 verbatim) ----
    #pragma unroll
    for (int mf = 0; mf < 4; mf++) {
        int o_lo = wm*64 + mf*16 + g;
        int o_hi = o_lo + 8;
        float bl = bias[b*CO + o_lo];
        float bh = bias[b*CO + o_hi];
        float sl = 0.f, ql = 0.f, sh = 0.f, qh = 0.f;
        #pragma unroll
        for (int bnl = 0; bnl < 4; bnl++) {
            int col = nT + wn*32 + bnl*8 + 2*tq;
            float v0 = acc[mf][bnl][0] + bl;
            float v1 = acc[mf][bnl][1] + bl;
            float v2 = acc[mf][bnl][2] + bh;
            float v3 = acc[mf][bnl][3] + bh;
            __half2 hlo = __floats2half2_rn(v0, v1);
            __half2 hhi = __floats2half2_rn(v2, v3);
            *(__half2*)(Yh + (size_t)b*CO*NN + (size_t)o_lo*NN + col) = hlo;
            *(__half2*)(Yh + (size_t)b*CO*NN + (size_t)o_hi*NN + col) = hhi;
            sl += v0 + v1; ql += v0*v0 + v1*v1;
            sh += v2 + v3; qh += v2*v2 + v3*v3;
        }
        #pragma unroll
        for (int off = 1; off <= 2; off <<= 1) {
            sl += __shfl_xor_sync(0xffffffffu, sl, off);
            ql += __shfl_xor_sync(0xffffffffu, ql, off);
            sh += __shfl_xor_sync(0xffffffffu, sh, off);
            qh += __shfl_xor_sync(0xffffffffu, qh, off);
        }
        if (tq == 0) {
            atomicAdd(&redS[o_lo], sl);
            atomicAdd(&redQ[o_lo], ql);
            atomicAdd(&redS[o_hi], sh);
            atomicAdd(&redQ[o_hi], qh);
        }
    }
    __syncthreads();
    atomicAdd(&sumOut[t], redS[t]);
    atomicAdd(&sqOut[t],  redQ[t]);
}

// ---------------- final: BN2 finalize + gelu in one pass, fp16 -> fp32 ----------------
__global__ void __launch_bounds__(256) final_kernel(
    const __half* __restrict__ y2h,
    const float* __restrict__ sum2, const float* __restrict__ sq2,
    const float* __restrict__ gamma, const float* __restrict__ beta,
    float* __restrict__ out)
{
    size_t i8 = (size_t)blockIdx.x * 256 + threadIdx.x;
    size_t total8 = (size_t)BB*CO*NN/8;
    if (i8 >= total8) return;
    uint4 u = ((const uint4*)y2h)[i8];
    size_t i = i8 * 8;
    int c = (int)((i >> 13) & 255);
    float m = sum2[c] * (1.0f/COUNT_BN);
    float v = sq2[c]  * (1.0f/COUNT_BN) - m*m;
    float inv = rsqrtf(v + 1e-5f);
    float a = gamma[c] * inv;
    float bo = beta[c] - a*m;
    const __half2* hp = (const __half2*)&u;
    float4 o0, o1;
    float2 f;
    f = __half22float2(hp[0]); o0.x = gelu_exact(fmaf(a, f.x, bo)); o0.y = gelu_exact(fmaf(a, f.y, bo));
    f = __half22float2(hp[1]); o0.z = gelu_exact(fmaf(a, f.x, bo)); o0.w = gelu_exact(fmaf(a, f.y, bo));
    f = __half22float2(hp[2]); o1.x = gelu_exact(fmaf(a, f.x, bo)); o1.y = gelu_exact(fmaf(a, f.y, bo));
    f = __half22float2(hp[3]); o1.z = gelu_exact(fmaf(a, f.x, bo)); o1.w = gelu_exact(fmaf(a, f.y, bo));
    ((float4*)out)[i8*2 + 0] = o0;
    ((float4*)out)[i8*2 + 1] = o1;
}

// ---------------- launch ----------------
extern "C" void kernel_launch(void* const* d_in, const int* in_sizes, int n_in,
                              void* d_out, int out_size)
{
    const float* xyz1    = (const float*)d_in[0];
    const float* xyz2    = (const float*)d_in[1];
    const float* points1 = (const float*)d_in[2];
    const float* points2 = (const float*)d_in[3];
    const float* t_embed = (const float*)d_in[4];
    const float* w_t1 = (const float*)d_in[5];
    const float* b_t1 = (const float*)d_in[6];
    const float* w_c1 = (const float*)d_in[7];
    const float* b_c1 = (const float*)d_in[8];
    const float* g1   = (const float*)d_in[9];
    const float* be1  = (const float*)d_in[10];
    const float* w_t2 = (const float*)d_in[11];
    const float* b_t2 = (const float*)d_in[12];
    const float* w_c2 = (const float*)d_in[13];
    const float* b_c2 = (const float*)d_in[14];
    const float* g2   = (const float*)d_in[15];
    const float* be2  = (const float*)d_in[16];
    float* out = (float*)d_out;

    float *p_bias1, *p_bias2;
    float *p_sum1, *p_sq1, *p_sum2, *p_sq2;
    __half *p_itph, *p_y1h, *p_y2h, *p_w1i, *p_w2i;
    cudaGetSymbolAddress((void**)&p_itph,  d_itph);
    cudaGetSymbolAddress((void**)&p_y1h,   d_y1h);
    cudaGetSymbolAddress((void**)&p_y2h,   d_y2h);
    cudaGetSymbolAddress((void**)&p_bias1, d_bias1);
    cudaGetSymbolAddress((void**)&p_bias2, d_bias2);
    cudaGetSymbolAddress((void**)&p_sum1,  d_sum1);
    cudaGetSymbolAddress((void**)&p_sq1,   d_sq1);
    cudaGetSymbolAddress((void**)&p_sum2,  d_sum2);
    cudaGetSymbolAddress((void**)&p_sq2,   d_sq2);
    cudaGetSymbolAddress((void**)&p_w1i,   d_w1img);
    cudaGetSymbolAddress((void**)&p_w2i,   d_w2img);

    // 1. mega-prep: top3 + transpose + weight perms + biases + stat zero
    mega_prep<<<MB_TOTAL, 256>>>(xyz1, xyz2, points2, t_embed,
                                 w_t1, b_t1, w_c1, b_c1,
                                 w_t2, b_t2, w_c2, b_c2);

    // 2. interpolation (float4 gather)
    interp_kernel<<<dim3(NN/32, BB), 256>>>();

    // 3. Layer 1: y1h = fp16(w_c1 @ [points1; itph] + bias1), stats -> sum1/sq1
    gemm_f16<CIN, false><<<dim3(NN/64, BB), 256>>>(
        p_w1i, points1, p_itph, p_y1h, p_bias1,
        nullptr, nullptr, nullptr, nullptr, p_sum1, p_sq1);

    // 4. Layer 2: y2h = fp16(w_c2 @ gelu(bn1(y1h)) + bias2); BN1 finalized in-kernel
    gemm_f16<CO, true><<<dim3(NN/64, BB), 256>>>(
        p_w2i, (const float*)nullptr, p_y1h, p_y2h, p_bias2,
        p_sum1, p_sq1, g1, be1, p_sum2, p_sq2);

    // 5. final: BN2 finalize + gelu -> fp32 out
    final_kernel<<<(unsigned)(((size_t)BB*CO*NN/8 + 255)/256), 256>>>(
        p_y2h, p_sum2, p_sq2, g2, be2, out);
}

// round 16
// speedup vs baseline: 1.3299x; 1.0290x over previous
#include <cuda_runtime.h>
#include <cuda_fp16.h>
#include <math.h>
#include <stdint.h>

#define BB   8
#define NN   8192
#define SS   2048
#define C1c  128
#define C2c  256
#define CIN  384
#define TT   256
#define CO   256
#define COUNT_BN (BB*NN)

// ---------------- scratch (device globals) ----------------
__device__ float  d_p2t[BB*SS*C2c];                 // points2 transposed (B,S,C2)
__device__ int    d_idx3[BB*NN*3];
__device__ float  d_w3[BB*NN*3];
__device__ __half d_itph[(size_t)BB*C2c*NN];        // interpolated channels, fp16
__device__ __half d_y1h[(size_t)BB*CO*NN];          // layer1 output, fp16
__device__ __half d_y2h[(size_t)BB*CO*NN];          // layer2 raw output, fp16
__device__ float  d_bias1[BB*CO];
__device__ float  d_bias2[BB*CO];
__device__ float  d_sum1[CO], d_sq1[CO], d_sum2[CO], d_sq2[CO];
// fp16 A images in m16n8k16 fragment order
__device__ __half d_w1img[CO*CIN];
__device__ __half d_w2img[CO*CO];

// mega-kernel block ranges
#define MB_TOP3   256                    // (NN/256)*BB = 32*8
#define MB_TRANS  4096                   // 64*8*BB
#define MB_PERM1  384                    // CO*CIN/256
#define MB_PERM2  256                    // CO*CO/256
#define MB_BIAS   BB
#define MB_TOTAL  (MB_TOP3 + MB_TRANS + MB_PERM1 + MB_PERM2 + MB_BIAS)   // 5000

__device__ __forceinline__ float gelu_exact(float x) {
    return 0.5f * x * (1.0f + erff(x * 0.7071067811865476f));
}
__device__ __forceinline__ uint32_t smem_u32(const void* p) {
    uint32_t a;
    asm("{ .reg .u64 tmp; cvta.to.shared.u64 tmp, %1; cvt.u32.u64 %0, tmp; }" : "=r"(a) : "l"(p));
    return a;
}
__device__ __forceinline__ void cp16(uint32_t dst, const void* src) {
    asm volatile("cp.async.cg.shared.global [%0], [%1], 16;" :: "r"(dst), "l"(src));
}
__device__ __forceinline__ void cp_commit() { asm volatile("cp.async.commit_group;" ::: "memory"); }
__device__ __forceinline__ void cp_wait0()  { asm volatile("cp.async.wait_group 0;" ::: "memory"); }

#define MMA_F16(d, a, b0, b1)                                                     \
    asm volatile("mma.sync.aligned.m16n8k16.row.col.f32.f16.f16.f32 "             \
                 "{%0,%1,%2,%3}, {%4,%5,%6,%7}, {%8,%9}, {%0,%1,%2,%3};"          \
                 : "+f"(d[0]), "+f"(d[1]), "+f"(d[2]), "+f"(d[3])                 \
                 : "r"(a.x), "r"(a.y), "r"(a.z), "r"(a.w), "r"(b0), "r"(b1))

// ---------------- weight permute body (fp16 m16n8k16 fragment order) ----------------
__device__ __forceinline__ void permA16_body(const float* __restrict__ w,
                                             __half* __restrict__ img, int K, int idx)
{
    int o = idx / K, k = idx % K;
    int bm = o >> 4, r = o & 15;
    int g = r & 7, hi = r >> 3;
    int kt = k >> 5, kl = k & 31;
    int bk = kl >> 4, kk = kl & 15;
    int tq  = (kk & 7) >> 1;
    int khi = kk >> 3;
    int klo = kk & 1;
    int lane = g*4 + tq;
    int reg  = hi + 2*khi;
    size_t uidx = ((size_t)(kt*16 + bm)*2 + bk)*128 + lane*4 + reg;
    img[uidx*2 + klo] = __float2half_rn(w[idx]);
}

// ---------------- mega: top3 + transpose + weight perms + t-cond biases + stat zero ----------------
__global__ void __launch_bounds__(256) mega_prep(
    const float* __restrict__ xyz1, const float* __restrict__ xyz2,
    const float* __restrict__ points2, const float* __restrict__ t_embed,
    const float* __restrict__ w_t1, const float* __restrict__ b_t1,
    const float* __restrict__ w_c1, const float* __restrict__ b_c1,
    const float* __restrict__ w_t2, const float* __restrict__ b_t2,
    const float* __restrict__ w_c2, const float* __restrict__ b_c2)
{
    __shared__ __align__(16) char smem_raw[32768];
    int blk = blockIdx.x, t = threadIdx.x;

    if (blk < MB_TOP3) {
        // ---- 3-NN top3 (1 point/thread, e-form, float4 smem) ----
        float4* sq = (float4*)smem_raw;           // SS entries = 32KB
        int b = blk >> 5;
        int nblk = blk & 31;
        const float* x2 = xyz2 + (size_t)b*SS*3;
        for (int i = t; i < SS; i += 256) {
            float a = x2[i*3+0], bb = x2[i*3+1], c = x2[i*3+2];
            float4 q;
            q.x = -2.0f*a; q.y = -2.0f*bb; q.z = -2.0f*c;
            q.w = a*a + bb*bb + c*c;
            sq[i] = q;
        }
        __syncthreads();
        int n = nblk * 256 + t;
        const float* p = xyz1 + ((size_t)b*NN + n)*3;
        float px = p[0], py = p[1], pz = p[2];
        float n1 = px*px + py*py + pz*pz;
        float e0 = 3.4e38f, e1 = 3.4e38f, e2 = 3.4e38f;
        int   i0 = 0, i1 = 0, i2 = 0;
        #pragma unroll 4
        for (int s = 0; s < SS; s++) {
            float4 q = sq[s];
            float e = fmaf(px, q.x, fmaf(py, q.y, fmaf(pz, q.z, q.w)));
            if (e < e2) {
                e2 = e; i2 = s;
                if (e2 < e1) {
                    float te = e1; e1 = e2; e2 = te;
                    int   ti = i1; i1 = i2; i2 = ti;
                    if (e1 < e0) {
                        te = e0; e0 = e1; e1 = te;
                        ti = i0; i0 = i1; i1 = ti;
                    }
                }
            }
        }
        float d0 = n1 + e0, d1 = n1 + e1, d2 = n1 + e2;
        float r0 = 1.f/(d0 + 1e-8f), r1 = 1.f/(d1 + 1e-8f), r2 = 1.f/(d2 + 1e-8f);
        float inv = 1.f/(r0 + r1 + r2);
        size_t base = ((size_t)b*NN + n)*3;
        d_idx3[base+0] = i0; d_idx3[base+1] = i1; d_idx3[base+2] = i2;
        d_w3[base+0] = r0*inv; d_w3[base+1] = r1*inv; d_w3[base+2] = r2*inv;
    } else if (blk < MB_TOP3 + MB_TRANS) {
        // ---- points2 transpose (B,C2,S) -> (B,S,C2) ----
        typedef float Tile[33];
        Tile* tile = (Tile*)smem_raw;
        int tb = blk - MB_TOP3;
        int b  = tb >> 9;
        int r  = tb & 511;
        int s0 = (r & 63) * 32;
        int c0 = (r >> 6) * 32;
        int tx = t & 31, ty = t >> 5;   // 32 x 8
        const float* src = points2 + (size_t)b*C2c*SS;
        float*       dst = d_p2t   + (size_t)b*SS*C2c;
        #pragma unroll
        for (int j = 0; j < 32; j += 8)
            tile[ty+j][tx] = src[(size_t)(c0+ty+j)*SS + s0 + tx];
        __syncthreads();
        #pragma unroll
        for (int j = 0; j < 32; j += 8)
            dst[(size_t)(s0+ty+j)*C2c + c0 + tx] = tile[tx][ty+j];
    } else if (blk < MB_TOP3 + MB_TRANS + MB_PERM1) {
        int idx = (blk - MB_TOP3 - MB_TRANS)*256 + t;
        permA16_body(w_c1, d_w1img, CIN, idx);
    } else if (blk < MB_TOP3 + MB_TRANS + MB_PERM1 + MB_PERM2) {
        int idx = (blk - MB_TOP3 - MB_TRANS - MB_PERM1)*256 + t;
        permA16_body(w_c2, d_w2img, CO, idx);
    } else {
        // ---- t-cond bias folding (256 threads) + stat zero ----
        float* g   = (float*)smem_raw;          // 256
        float* te1 = g + TT;                    // 384
        float* te2 = te1 + CIN;                 // 256
        int b = blk - (MB_TOP3 + MB_TRANS + MB_PERM1 + MB_PERM2);
        g[t] = gelu_exact(t_embed[b*TT + t]);
        __syncthreads();
        for (int c = t; c < CIN; c += 256) {
            float s = b_t1[c];
            const float* w = w_t1 + (size_t)c*TT;
            #pragma unroll 8
            for (int k = 0; k < TT; k++) s = fmaf(g[k], w[k], s);
            te1[c] = s;
        }
        {
            float s = b_t2[t];
            const float* w = w_t2 + (size_t)t*TT;
            #pragma unroll 8
            for (int k = 0; k < TT; k++) s = fmaf(g[k], w[k], s);
            te2[t] = s;
        }
        __syncthreads();
        {
            float s1 = b_c1[t];
            const float* w1 = w_c1 + (size_t)t*CIN;
            #pragma unroll 8
            for (int k = 0; k < CIN; k++) s1 = fmaf(te1[k], w1[k], s1);
            d_bias1[b*CO + t] = s1;
            float s2 = b_c2[t];
            const float* w2 = w_c2 + (size_t)t*CO;
            #pragma unroll 8
            for (int k = 0; k < CO; k++) s2 = fmaf(te2[k], w2[k], s2);
            d_bias2[b*CO + t] = s2;
        }
        if (b == 0) {
            d_sum1[t] = 0.f; d_sq1[t] = 0.f; d_sum2[t] = 0.f; d_sq2[t] = 0.f;
        }
    }
}

// ---------------- 3-NN interpolation into d_itph, float4 gather ----------------
__global__ void __launch_bounds__(256) interp_kernel()
{
    __shared__ __half sc[C2c][34];
    __shared__ int    sidx[32*3];
    __shared__ float  swt[32*3];
    int b  = blockIdx.y;
    int n0 = blockIdx.x * 32;
    int t  = threadIdx.x;
    if (t < 96) {
        size_t base = ((size_t)b*NN + n0)*3;
        sidx[t] = d_idx3[base + t];
        swt[t]  = d_w3[base + t];
    }
    __syncthreads();
    const float* p2t = d_p2t + (size_t)b*SS*C2c;
    int q  = t & 63;          // channel quad
    int pg = t >> 6;          // point group (0..3)
    int c0 = q * 4;
    #pragma unroll
    for (int p = 0; p < 8; p++) {
        int nl = pg + p*4;    // point 0..31
        int   j0 = sidx[nl*3+0], j1 = sidx[nl*3+1], j2 = sidx[nl*3+2];
        float w0 = swt[nl*3+0],  w1 = swt[nl*3+1],  w2 = swt[nl*3+2];
        float4 v0 = *(const float4*)(p2t + (size_t)j0*C2c + c0);
        float4 v1 = *(const float4*)(p2t + (size_t)j1*C2c + c0);
        float4 v2 = *(const float4*)(p2t + (size_t)j2*C2c + c0);
        float r0 = fmaf(w2, v2.x, fmaf(w1, v1.x, w0*v0.x));
        float r1 = fmaf(w2, v2.y, fmaf(w1, v1.y, w0*v0.y));
        float r2 = fmaf(w2, v2.z, fmaf(w1, v1.z, w0*v0.z));
        float r3 = fmaf(w2, v2.w, fmaf(w1, v1.w, w0*v0.w));
        sc[c0+0][nl] = __float2half_rn(r0);
        sc[c0+1][nl] = __float2half_rn(r1);
        sc[c0+2][nl] = __float2half_rn(r2);
        sc[c0+3][nl] = __float2half_rn(r3);
    }
    __syncthreads();
    __half* xout = d_itph + (size_t)b*C2c*NN + n0;
    int nl2 = (t & 15) * 2;
    int cc0 = t >> 4;
    #pragma unroll
    for (int c = cc0; c < C2c; c += 16) {
        __half2 hv;
        hv.x = sc[c][nl2];
        hv.y = sc[c][nl2 + 1];
        *(__half2*)(xout + (size_t)c*NN + nl2) = hv;
    }
}

// ---------------- fp16 tensor-core GEMM (R15 + PRMT repack for pure-fp16 chunks) ----------------
template<int KTOT, bool L2MODE>
__global__ void __launch_bounds__(256) gemm_f16(
    const __half* __restrict__ AimgH,
    const float* __restrict__ Xp1,
    const __half* __restrict__ Xh,
    __half* __restrict__ Yh,
    const float* __restrict__ bias,
    const float* __restrict__ sumIn, const float* __restrict__ sqIn,
    const float* __restrict__ gamma, const float* __restrict__ beta,
    float* __restrict__ sumOut, float* __restrict__ sqOut)
{
    constexpr int NC = KTOT / 32;
    __shared__ __align__(16) uint4    As[2][1024];
    __shared__ __align__(16) uint32_t Bs[2][1024];
    __shared__ float redS[CO], redQ[CO];
    __shared__ float sA[CO], sB[CO];

    const uint32_t* Aimg = (const uint32_t*)AimgH;
    int t = threadIdx.x, l = t & 31, w = t >> 5;
    int wm = w >> 1, wn = w & 1;
    int g = l >> 2, tq = l & 3;
    int b = blockIdx.y, nT = blockIdx.x * 64;

    redS[t] = 0.f; redQ[t] = 0.f;
    if (L2MODE) {
        float m = sumIn[t] * (1.0f/COUNT_BN);
        float v = sqIn[t]  * (1.0f/COUNT_BN) - m*m;
        float inv = rsqrtf(v + 1e-5f);
        float a = gamma[t] * inv;
        sA[t] = a;
        sB[t] = beta[t] - a*m;
    }
    __syncthreads();

    int kp = t >> 4, n4 = t & 15;

    // hoisted per-lane B-fragment word offsets
    uint32_t Doff[4];
    #pragma unroll
    for (int bnl = 0; bnl < 4; bnl++)
        Doff[bnl] = (uint32_t)(tq*64 + wn*32 + ((bnl ^ tq) << 3) + g);

    float acc[4][4][4];
    #pragma unroll
    for (int i = 0; i < 4; i++)
        #pragma unroll
        for (int j = 0; j < 4; j++)
            #pragma unroll
            for (int r = 0; r < 4; r++) acc[i][j][r] = 0.f;

    // pv carries either floats (fp32 src / pre-gelu floats) or raw fp16x2 bits
    float pv[8];
    auto stageB = [&](int c) {
        int k0 = c*32 + 2*kp;
        bool useH = L2MODE || (k0 >= C1c);
        if (useH) {
            int kk = L2MODE ? k0 : (k0 - C1c);
            const __half* bh = Xh + (size_t)b*C2c*NN + (size_t)kk*NN + nT + 4*n4;
            uint2 u0 = *(const uint2*)bh;
            uint2 u1 = *(const uint2*)(bh + NN);
            if (L2MODE) {
                __half2 h;
                h = *(__half2*)&u0.x; pv[0] = __low2float(h); pv[1] = __high2float(h);
                h = *(__half2*)&u0.y; pv[2] = __low2float(h); pv[3] = __high2float(h);
                h = *(__half2*)&u1.x; pv[4] = __low2float(h); pv[5] = __high2float(h);
                h = *(__half2*)&u1.y; pv[6] = __low2float(h); pv[7] = __high2float(h);
            } else {
                // raw bits pass-through (repacked with PRMT in storeB)
                pv[0] = __uint_as_float(u0.x);
                pv[1] = __uint_as_float(u0.y);
                pv[2] = __uint_as_float(u1.x);
                pv[3] = __uint_as_float(u1.y);
            }
        } else {
            const float* base = Xp1 + (size_t)b*C1c*NN + (size_t)k0*NN + nT + 4*n4;
            float4 v0 = *(const float4*)base;
            float4 v1 = *(const float4*)(base + NN);
            pv[0] = v0.x; pv[1] = v0.y; pv[2] = v0.z; pv[3] = v0.w;
            pv[4] = v1.x; pv[5] = v1.y; pv[6] = v1.z; pv[7] = v1.w;
        }
    };
    auto storeB = [&](int c, int buf) {
        uint4 u;
        if (L2MODE) {
            float f[8];
            #pragma unroll
            for (int j = 0; j < 8; j++) f[j] = pv[j];
            int kg0 = c*32 + 2*kp;
            float a0 = sA[kg0],   b0 = sB[kg0];
            float a1 = sA[kg0+1], b1 = sB[kg0+1];
            #pragma unroll
            for (int j = 0; j < 4; j++) f[j]   = gelu_exact(fmaf(a0, f[j],   b0));
            #pragma unroll
            for (int j = 0; j < 4; j++) f[j+4] = gelu_exact(fmaf(a1, f[j+4], b1));
            __half2 h;
            h = __floats2half2_rn(f[0], f[4]); u.x = *(uint32_t*)&h;
            h = __floats2half2_rn(f[1], f[5]); u.y = *(uint32_t*)&h;
            h = __floats2half2_rn(f[2], f[6]); u.z = *(uint32_t*)&h;
            h = __floats2half2_rn(f[3], f[7]); u.w = *(uint32_t*)&h;
        } else if (c*32 + 2*kp >= C1c) {
            // fp16 source: exact PRMT repack {k,n} x {k+1,n} -> {n interleave}
            uint32_t a0 = __float_as_uint(pv[0]);   // k  : n0 n1
            uint32_t a1 = __float_as_uint(pv[1]);   // k  : n2 n3
            uint32_t b0 = __float_as_uint(pv[2]);   // k+1: n0 n1
            uint32_t b1 = __float_as_uint(pv[3]);   // k+1: n2 n3
            u.x = __byte_perm(a0, b0, 0x5410);
            u.y = __byte_perm(a0, b0, 0x7632);
            u.z = __byte_perm(a1, b1, 0x5410);
            u.w = __byte_perm(a1, b1, 0x7632);
        } else {
            __half2 h;
            h = __floats2half2_rn(pv[0], pv[4]); u.x = *(uint32_t*)&h;
            h = __floats2half2_rn(pv[1], pv[5]); u.y = *(uint32_t*)&h;
            h = __floats2half2_rn(pv[2], pv[6]); u.z = *(uint32_t*)&h;
            h = __floats2half2_rn(pv[3], pv[7]); u.w = *(uint32_t*)&h;
        }
        ((uint4*)Bs[buf])[kp*16 + (n4 ^ ((kp & 3) << 1))] = u;
    };
    auto stageA = [&](int c, int buf) {
        const uint32_t* src = Aimg + (size_t)c*4096 + t*4;
        uint32_t base = smem_u32(&As[buf][0]);
        #pragma unroll
        for (int j = 0; j < 4; j++)
            cp16(base + (uint32_t)(t + j*256)*16u, src + j*1024);
    };
    auto compute = [&](int buf) {
        const uint32_t* bs = Bs[buf];
        uint4 af[4][2];
        #pragma unroll
        for (int mf = 0; mf < 4; mf++)
            #pragma unroll
            for (int bk = 0; bk < 2; bk++)
                af[mf][bk] = As[buf][((wm*4 + mf)*2 + bk)*32 + l];
        uint32_t bf[4][2][2];
        #pragma unroll
        for (int bnl = 0; bnl < 4; bnl++) {
            #pragma unroll
            for (int bk = 0; bk < 2; bk++) {
                bf[bnl][bk][0] = bs[Doff[bnl] + bk*512];
                bf[bnl][bk][1] = bs[Doff[bnl] + bk*512 + 256];
            }
        }
        #pragma unroll
        for (int mf = 0; mf < 4; mf++)
            #pragma unroll
            for (int bnl = 0; bnl < 4; bnl++)
                #pragma unroll
                for (int bk = 0; bk < 2; bk++)
                    MMA_F16(acc[mf][bnl], af[mf][bk], bf[bnl][bk][0], bf[bnl][bk][1]);
    };

    stageB(0);
    stageA(0, 0); cp_commit();
    storeB(0, 0);
    #pragma unroll 2
    for (int c = 0; c < NC; c++) {
        int buf = c & 1;
        cp_wait0();
        __syncthreads();
        if (c + 1 < NC) { stageB(c + 1); stageA(c + 1, buf ^ 1); cp_commit(); }
        compute(buf);
        if (c + 1 < NC) storeB(c + 1, buf ^ 1);
    }

    // ---- epilogue: bias, fp16 store, stats ----
    #pragma unroll
    for (int mf = 0; mf < 4; mf++) {
        int o_lo = wm*64 + mf*16 + g;
        int o_hi = o_lo + 8;
        float bl = bias[b*CO + o_lo];
        float bh = bias[b*CO + o_hi];
        float sl = 0.f, ql = 0.f, sh = 0.f, qh = 0.f;
        #pragma unroll
        for (int bnl = 0; bnl < 4; bnl++) {
            int col = nT + wn*32 + bnl*8 + 2*tq;
            float v0 = acc[mf][bnl][0] + bl;
            float v1 = acc[mf][bnl][1] + bl;
            float v2 = acc[mf][bnl][2] + bh;
            float v3 = acc[mf][bnl][3] + bh;
            __half2 hlo = __floats2half2_rn(v0, v1);
            __half2 hhi = __floats2half2_rn(v2, v3);
            *(__half2*)(Yh + (size_t)b*CO*NN + (size_t)o_lo*NN + col) = hlo;
            *(__half2*)(Yh + (size_t)b*CO*NN + (size_t)o_hi*NN + col) = hhi;
            sl += v0 + v1; ql += v0*v0 + v1*v1;
            sh += v2 + v3; qh += v2*v2 + v3*v3;
        }
        #pragma unroll
        for (int off = 1; off <= 2; off <<= 1) {
            sl += __shfl_xor_sync(0xffffffffu, sl, off);
            ql += __shfl_xor_sync(0xffffffffu, ql, off);
            sh += __shfl_xor_sync(0xffffffffu, sh, off);
            qh += __shfl_xor_sync(0xffffffffu, qh, off);
        }
        if (tq == 0) {
            atomicAdd(&redS[o_lo], sl);
            atomicAdd(&redQ[o_lo], ql);
            atomicAdd(&redS[o_hi], sh);
            atomicAdd(&redQ[o_hi], qh);
        }
    }
    __syncthreads();
    atomicAdd(&sumOut[t], redS[t]);
    atomicAdd(&sqOut[t],  redQ[t]);
}

// ---------------- final: BN2 finalize + gelu in one pass, fp16 -> fp32 ----------------
__global__ void __launch_bounds__(256) final_kernel(
    const __half* __restrict__ y2h,
    const float* __restrict__ sum2, const float* __restrict__ sq2,
    const float* __restrict__ gamma, const float* __restrict__ beta,
    float* __restrict__ out)
{
    size_t i8 = (size_t)blockIdx.x * 256 + threadIdx.x;
    size_t total8 = (size_t)BB*CO*NN/8;
    if (i8 >= total8) return;
    uint4 u = ((const uint4*)y2h)[i8];
    size_t i = i8 * 8;
    int c = (int)((i >> 13) & 255);
    float m = sum2[c] * (1.0f/COUNT_BN);
    float v = sq2[c]  * (1.0f/COUNT_BN) - m*m;
    float inv = rsqrtf(v + 1e-5f);
    float a = gamma[c] * inv;
    float bo = beta[c] - a*m;
    const __half2* hp = (const __half2*)&u;
    float4 o0, o1;
    float2 f;
    f = __half22float2(hp[0]); o0.x = gelu_exact(fmaf(a, f.x, bo)); o0.y = gelu_exact(fmaf(a, f.y, bo));
    f = __half22float2(hp[1]); o0.z = gelu_exact(fmaf(a, f.x, bo)); o0.w = gelu_exact(fmaf(a, f.y, bo));
    f = __half22float2(hp[2]); o1.x = gelu_exact(fmaf(a, f.x, bo)); o1.y = gelu_exact(fmaf(a, f.y, bo));
    f = __half22float2(hp[3]); o1.z = gelu_exact(fmaf(a, f.x, bo)); o1.w = gelu_exact(fmaf(a, f.y, bo));
    ((float4*)out)[i8*2 + 0] = o0;
    ((float4*)out)[i8*2 + 1] = o1;
}

// ---------------- launch ----------------
extern "C" void kernel_launch(void* const* d_in, const int* in_sizes, int n_in,
                              void* d_out, int out_size)
{
    const float* xyz1    = (const float*)d_in[0];
    const float* xyz2    = (const float*)d_in[1];
    const float* points1 = (const float*)d_in[2];
    const float* points2 = (const float*)d_in[3];
    const float* t_embed = (const float*)d_in[4];
    const float* w_t1 = (const float*)d_in[5];
    const float* b_t1 = (const float*)d_in[6];
    const float* w_c1 = (const float*)d_in[7];
    const float* b_c1 = (const float*)d_in[8];
    const float* g1   = (const float*)d_in[9];
    const float* be1  = (const float*)d_in[10];
    const float* w_t2 = (const float*)d_in[11];
    const float* b_t2 = (const float*)d_in[12];
    const float* w_c2 = (const float*)d_in[13];
    const float* b_c2 = (const float*)d_in[14];
    const float* g2   = (const float*)d_in[15];
    const float* be2  = (const float*)d_in[16];
    float* out = (float*)d_out;

    float *p_bias1, *p_bias2;
    float *p_sum1, *p_sq1, *p_sum2, *p_sq2;
    __half *p_itph, *p_y1h, *p_y2h, *p_w1i, *p_w2i;
    cudaGetSymbolAddress((void**)&p_itph,  d_itph);
    cudaGetSymbolAddress((void**)&p_y1h,   d_y1h);
    cudaGetSymbolAddress((void**)&p_y2h,   d_y2h);
    cudaGetSymbolAddress((void**)&p_bias1, d_bias1);
    cudaGetSymbolAddress((void**)&p_bias2, d_bias2);
    cudaGetSymbolAddress((void**)&p_sum1,  d_sum1);
    cudaGetSymbolAddress((void**)&p_sq1,   d_sq1);
    cudaGetSymbolAddress((void**)&p_sum2,  d_sum2);
    cudaGetSymbolAddress((void**)&p_sq2,   d_sq2);
    cudaGetSymbolAddress((void**)&p_w1i,   d_w1img);
    cudaGetSymbolAddress((void**)&p_w2i,   d_w2img);

    // 1. mega-prep: top3 + transpose + weight perms + biases + stat zero
    mega_prep<<<MB_TOTAL, 256>>>(xyz1, xyz2, points2, t_embed,
                                 w_t1, b_t1, w_c1, b_c1,
                                 w_t2, b_t2, w_c2, b_c2);

    // 2. interpolation (float4 gather)
    interp_kernel<<<dim3(NN/32, BB), 256>>>();

    // 3. Layer 1: y1h = fp16(w_c1 @ [points1; itph] + bias1), stats -> sum1/sq1
    gemm_f16<CIN, false><<<dim3(NN/64, BB), 256>>>(
        p_w1i, points1, p_itph, p_y1h, p_bias1,
        nullptr, nullptr, nullptr, nullptr, p_sum1, p_sq1);

    // 4. Layer 2: y2h = fp16(w_c2 @ gelu(bn1(y1h)) + bias2); BN1 finalized in-kernel
    gemm_f16<CO, true><<<dim3(NN/64, BB), 256>>>(
        p_w2i, (const float*)nullptr, p_y1h, p_y2h, p_bias2,
        p_sum1, p_sq1, g1, be1, p_sum2, p_sq2);

    // 5. final: BN2 finalize + gelu -> fp32 out
    final_kernel<<<(unsigned)(((size_t)BB*CO*NN/8 + 255)/256), 256>>>(
        p_y2h, p_sum2, p_sq2, g2, be2, out);
}